// round 10
// baseline (speedup 1.0000x reference)
#include <cuda_runtime.h>
#include <cuda_bf16.h>
#include <cuda_fp16.h>
#include <cstdint>

#define N_NODES 50000
#define N_EDGES 850000
#define F_INF   256
#define FH      64
#define NHEADS  8
#define NCLASSF 40
#define ALPHAF  0.2f
#define D1      (NHEADS * FH)   // 512
#define MSPLIT  25088           // 196 * 128, half boundary on tile grid

// ---------------- device scratch ----------------
__device__ __half g_H1h[(size_t)N_NODES * D1];   // layer-1 features (fp16)
__device__ __half g_H2h[(size_t)N_NODES * FH];   // layer-2 features (fp16)
__device__ float g_S1s[N_NODES * NHEADS];
__device__ float g_S1d[N_NODES * NHEADS];
__device__ float g_S2s[N_NODES];
__device__ float g_S2d[N_NODES];
__device__ int   g_rowptr[N_NODES + 1];
__device__ int   g_cnt[N_NODES];
__device__ int   g_pos[N_NODES];
__device__ int   g_dsts[N_EDGES];
// bf16 split operands
__device__ __nv_bfloat16 g_xh[(size_t)N_NODES * F_INF];
__device__ __nv_bfloat16 g_xl[(size_t)N_NODES * F_INF];
__device__ __nv_bfloat16 g_wth[NHEADS * FH * F_INF];
__device__ __nv_bfloat16 g_wtl[NHEADS * FH * F_INF];
__device__ __nv_bfloat16 g_woth[FH * D1];
__device__ __nv_bfloat16 g_wotl[FH * D1];
__device__ __nv_bfloat16 g_xch[(size_t)N_NODES * D1];
__device__ __nv_bfloat16 g_xcl[(size_t)N_NODES * D1];

__device__ __forceinline__ float leakyv(float v) { return v > 0.f ? v : ALPHAF * v; }
__device__ __forceinline__ float eluv(float v)   { return v > 0.f ? v : expm1f(v); }
__device__ __forceinline__ float4 ldh4(const __half* p) {
    uint2 u = *(const uint2*)p;
    __half2 h0 = *reinterpret_cast<__half2*>(&u.x);
    __half2 h1 = *reinterpret_cast<__half2*>(&u.y);
    float2 f0 = __half22float2(h0), f1 = __half22float2(h1);
    return make_float4(f0.x, f0.y, f1.x, f1.y);
}

// ---------------- CSR build ----------------
__global__ void k_zero_cnt() {
    int i = blockIdx.x * blockDim.x + threadIdx.x;
    if (i < N_NODES) g_cnt[i] = 0;
}
__global__ void k_hist(const int* __restrict__ src) {
    int e = blockIdx.x * blockDim.x + threadIdx.x;
    if (e < N_EDGES) atomicAdd(&g_cnt[src[e]], 1);
}
__global__ __launch_bounds__(1024) void k_scan() {
    __shared__ int s[1024];
    const int CH = 49;
    int t = threadIdx.x;
    int start = t * CH;
    int end = start + CH; if (end > N_NODES) end = N_NODES;
    int sum = 0;
    for (int i = start; i < end; i++) sum += g_cnt[i];
    s[t] = sum;
    __syncthreads();
    for (int off = 1; off < 1024; off <<= 1) {
        int v = (t >= off) ? s[t - off] : 0;
        __syncthreads();
        s[t] += v;
        __syncthreads();
    }
    int run = (t == 0) ? 0 : s[t - 1];
    for (int i = start; i < end; i++) {
        g_rowptr[i] = run;
        g_pos[i] = run;
        run += g_cnt[i];
    }
    if (t == 0) g_rowptr[N_NODES] = s[1023];
}
__global__ void k_scatter(const int* __restrict__ src, const int* __restrict__ dst) {
    int e = blockIdx.x * blockDim.x + threadIdx.x;
    if (e < N_EDGES) {
        int p = atomicAdd(&g_pos[src[e]], 1);
        g_dsts[p] = dst[e];
    }
}

// ---------------- bf16 hi/lo splits ----------------
__global__ void k_split_x(const float* __restrict__ x, __nv_bfloat16* __restrict__ oh,
                          __nv_bfloat16* __restrict__ ol, int n4) {
    int i = blockIdx.x * blockDim.x + threadIdx.x;
    if (i >= n4) return;
    float4 v = ((const float4*)x)[i];
    __nv_bfloat16 h0 = __float2bfloat16(v.x), h1 = __float2bfloat16(v.y);
    __nv_bfloat16 h2 = __float2bfloat16(v.z), h3 = __float2bfloat16(v.w);
    __nv_bfloat16 l0 = __float2bfloat16(v.x - __bfloat162float(h0));
    __nv_bfloat16 l1 = __float2bfloat16(v.y - __bfloat162float(h1));
    __nv_bfloat16 l2 = __float2bfloat16(v.z - __bfloat162float(h2));
    __nv_bfloat16 l3 = __float2bfloat16(v.w - __bfloat162float(h3));
    __nv_bfloat162* ph = (__nv_bfloat162*)(oh) + i * 2;
    __nv_bfloat162* pl = (__nv_bfloat162*)(ol) + i * 2;
    ph[0] = __halves2bfloat162(h0, h1); ph[1] = __halves2bfloat162(h2, h3);
    pl[0] = __halves2bfloat162(l0, l1); pl[1] = __halves2bfloat162(l2, l3);
}
// W[h][k][n] (fp32) -> out[h][n][k] bf16 hi/lo
__global__ void k_split_wt(const float* __restrict__ W, __nv_bfloat16* __restrict__ oh,
                           __nv_bfloat16* __restrict__ ol) {
    int i = blockIdx.x * blockDim.x + threadIdx.x;
    if (i >= NHEADS * F_INF * FH) return;
    int h = i / (F_INF * FH), r = i % (F_INF * FH), k = r / FH, n = r % FH;
    float v = W[i];
    __nv_bfloat16 hh = __float2bfloat16(v);
    __nv_bfloat16 ll = __float2bfloat16(v - __bfloat162float(hh));
    size_t o = (size_t)(h * FH + n) * F_INF + k;
    oh[o] = hh; ol[o] = ll;
}
// Wo[k][n] -> out[n][k]
__global__ void k_split_wot(const float* __restrict__ Wo, __nv_bfloat16* __restrict__ oh,
                            __nv_bfloat16* __restrict__ ol) {
    int i = blockIdx.x * blockDim.x + threadIdx.x;
    if (i >= D1 * FH) return;
    int k = i / FH, n = i % FH;
    float v = Wo[i];
    __nv_bfloat16 hh = __float2bfloat16(v);
    __nv_bfloat16 ll = __float2bfloat16(v - __bfloat162float(hh));
    size_t o = (size_t)n * D1 + k;
    oh[o] = hh; ol[o] = ll;
}

// ---------------- mma.sync bf16x3 GEMM, 3-stage cp.async pipeline ----------
#define BM 128
#define BN 64
#define BK 32
#define AST 40                      // padded row stride in bf16 (80B)
#define STG 30720                   // bytes per pipeline stage
#define NSTAGE 3
#define OFF_AH 0
#define OFF_AL 10240
#define OFF_BH 20480
#define OFF_BL 25600
#define GSMEM  (NSTAGE * STG + 2048)

__device__ __forceinline__ void mma16816(float* d, const uint32_t* a, const uint32_t* b) {
    asm volatile(
        "mma.sync.aligned.m16n8k16.row.col.f32.bf16.bf16.f32 "
        "{%0,%1,%2,%3},{%4,%5,%6,%7},{%8,%9},{%0,%1,%2,%3};"
        : "+f"(d[0]), "+f"(d[1]), "+f"(d[2]), "+f"(d[3])
        : "r"(a[0]), "r"(a[1]), "r"(a[2]), "r"(a[3]), "r"(b[0]), "r"(b[1]));
}
__device__ __forceinline__ void ldsm4(uint32_t* r, const void* p) {
    uint32_t addr = (uint32_t)__cvta_generic_to_shared(p);
    asm volatile("ldmatrix.sync.aligned.m8n8.x4.shared.b16 {%0,%1,%2,%3}, [%4];"
                 : "=r"(r[0]), "=r"(r[1]), "=r"(r[2]), "=r"(r[3]) : "r"(addr));
}
__device__ __forceinline__ void cp_async16(uint32_t saddr, const void* g, int sz) {
    asm volatile("cp.async.cg.shared.global [%0], [%1], 16, %2;"
                 :: "r"(saddr), "l"(g), "r"(sz));
}
#define CP_COMMIT() asm volatile("cp.async.commit_group;")
#define CP_WAIT0()  asm volatile("cp.async.wait_group 0;")
#define CP_WAIT1()  asm volatile("cp.async.wait_group 1;")

// Output always packed fp16 (Ch). m_off shifts the tile range for pipelined halves.
__global__ __launch_bounds__(256) void k_gemm_mma(
    const __nv_bfloat16* __restrict__ Ah, const __nv_bfloat16* __restrict__ Al,
    const __nv_bfloat16* __restrict__ Bh, const __nv_bfloat16* __restrict__ Bl,
    int M, int K, int m_off, __half* __restrict__ Ch, int ldc,
    const float* __restrict__ att, float* __restrict__ Ss, float* __restrict__ Sd,
    int sstride)
{
    extern __shared__ char sm[];
    uint32_t sbase = (uint32_t)__cvta_generic_to_shared(sm);
    float* redp = (float*)(sm + NSTAGE * STG);   // [2][BM][2]

    int tid = threadIdx.x, lane = tid & 31, wid = tid >> 5;
    int wm = wid & 3, wn = wid >> 2;        // warp grid 4(m) x 2(n)
    int m0 = blockIdx.x * BM + m_off;
    int bidy = blockIdx.y;
    Bh += (size_t)bidy * FH * K;
    Bl += (size_t)bidy * FH * K;
    att += bidy * 2 * FH;
    int coloff = bidy * FH;

    float acc[2][4][4];
#pragma unroll
    for (int i = 0; i < 2; i++)
#pragma unroll
        for (int j = 0; j < 4; j++)
#pragma unroll
            for (int l = 0; l < 4; l++) acc[i][j][l] = 0.f;

    int q = lane >> 2, cq = (lane & 3) * 2;

    // per-thread staging map: 6 chunks of 16B; sel: 0 Ah,1 Al,2 Bh,3 Bl
    int st_row[6], st_q[6], st_sel[6];
#pragma unroll
    for (int l = 0; l < 6; l++) {
        int it = tid + l * 256;
        if (it < 1024) {
            int p = it >> 9, i = it & 511;
            st_sel[l] = p; st_row[l] = i >> 2; st_q[l] = i & 3;
        } else {
            int j = it - 1024, p = j >> 8, i = j & 255;
            st_sel[l] = 2 + p; st_row[l] = i >> 2; st_q[l] = i & 3;
        }
    }
    const int seloff[4] = {OFF_AH, OFF_AL, OFF_BH, OFF_BL};

    auto issue_tile = [&](int k0, int slot) {
        uint32_t bo = sbase + slot * STG;
#pragma unroll
        for (int l = 0; l < 6; l++) {
            int row = st_row[l], qq = st_q[l], sel = st_sel[l];
            const __nv_bfloat16* g;
            int sz = 16;
            if (sel < 2) {
                int m = m0 + row;
                if (m >= M) { sz = 0; m = 0; }
                g = (sel ? Al : Ah) + (size_t)m * K + k0 + qq * 8;
            } else {
                g = (sel == 2 ? Bh : Bl) + (size_t)row * K + k0 + qq * 8;
            }
            cp_async16(bo + seloff[sel] + row * 80 + qq * 16, g, sz);
        }
    };

    int nk = K / BK;
    issue_tile(0, 0);
    CP_COMMIT();
    if (nk > 1) { issue_tile(BK, 1); CP_COMMIT(); }

    int arow = lane & 15, ak = (lane >> 4) * 8;
    int brow = (lane & 7) + ((lane >> 4) << 3), bk = ((lane >> 3) & 1) * 8;

    for (int i = 0; i < nk; i++) {
        if (i + 2 < nk) CP_WAIT1(); else CP_WAIT0();
        __syncthreads();
        if (i + 2 < nk) {
            issue_tile((i + 2) * BK, (i + 2) % NSTAGE);
            CP_COMMIT();
        }
        const char* sb = sm + (i % NSTAGE) * STG;
        const __nv_bfloat16* sAh = (const __nv_bfloat16*)(sb + OFF_AH);
        const __nv_bfloat16* sAl = (const __nv_bfloat16*)(sb + OFF_AL);
        const __nv_bfloat16* sBh = (const __nv_bfloat16*)(sb + OFF_BH);
        const __nv_bfloat16* sBl = (const __nv_bfloat16*)(sb + OFF_BL);

#pragma unroll
        for (int kf = 0; kf < 2; kf++) {
            int c0 = kf * 16;
            uint32_t ah[2][4], al[2][4], bhf[4][2], blf[4][2];
#pragma unroll
            for (int mf = 0; mf < 2; mf++) {
                int r = (wm * 32 + mf * 16 + arow) * AST + c0 + ak;
                ldsm4(ah[mf], &sAh[r]);
                ldsm4(al[mf], &sAl[r]);
            }
#pragma unroll
            for (int nfp = 0; nfp < 2; nfp++) {
                int r = (wn * 32 + nfp * 16 + brow) * AST + c0 + bk;
                uint32_t tb[4], tl[4];
                ldsm4(tb, &sBh[r]);
                ldsm4(tl, &sBl[r]);
                bhf[2 * nfp][0] = tb[0]; bhf[2 * nfp][1] = tb[1];
                bhf[2 * nfp + 1][0] = tb[2]; bhf[2 * nfp + 1][1] = tb[3];
                blf[2 * nfp][0] = tl[0]; blf[2 * nfp][1] = tl[1];
                blf[2 * nfp + 1][0] = tl[2]; blf[2 * nfp + 1][1] = tl[3];
            }
#pragma unroll
            for (int mf = 0; mf < 2; mf++)
#pragma unroll
                for (int nf = 0; nf < 4; nf++) {
                    mma16816(acc[mf][nf], ah[mf], bhf[nf]);
                    mma16816(acc[mf][nf], ah[mf], blf[nf]);
                    mma16816(acc[mf][nf], al[mf], bhf[nf]);
                }
        }
    }

    // ---- epilogue: store C packed fp16, fused score dot products ----
    float sp[2][2][2];
#pragma unroll
    for (int mf = 0; mf < 2; mf++)
#pragma unroll
        for (int h = 0; h < 2; h++) { sp[mf][h][0] = 0.f; sp[mf][h][1] = 0.f; }

#pragma unroll
    for (int mf = 0; mf < 2; mf++) {
        int r = wm * 32 + mf * 16 + q;
        int mr = m0 + r;
#pragma unroll
        for (int nf = 0; nf < 4; nf++) {
            int c = wn * 32 + nf * 8 + cq;
            float d0 = acc[mf][nf][0], d1 = acc[mf][nf][1];
            float d2 = acc[mf][nf][2], d3 = acc[mf][nf][3];
            if (mr < M)
                *(__half2*)&Ch[(size_t)mr * ldc + coloff + c] = __floats2half2_rn(d0, d1);
            if (mr + 8 < M)
                *(__half2*)&Ch[(size_t)(mr + 8) * ldc + coloff + c] = __floats2half2_rn(d2, d3);
            float a0 = att[c], a1 = att[c + 1], a2 = att[FH + c], a3 = att[FH + c + 1];
            sp[mf][0][0] = fmaf(d0, a0, fmaf(d1, a1, sp[mf][0][0]));
            sp[mf][0][1] = fmaf(d0, a2, fmaf(d1, a3, sp[mf][0][1]));
            sp[mf][1][0] = fmaf(d2, a0, fmaf(d3, a1, sp[mf][1][0]));
            sp[mf][1][1] = fmaf(d2, a2, fmaf(d3, a3, sp[mf][1][1]));
        }
    }
#pragma unroll
    for (int mf = 0; mf < 2; mf++)
#pragma unroll
        for (int h = 0; h < 2; h++)
#pragma unroll
            for (int sc = 0; sc < 2; sc++) {
                float v = sp[mf][h][sc];
                v += __shfl_xor_sync(0xffffffffu, v, 1);
                v += __shfl_xor_sync(0xffffffffu, v, 2);
                sp[mf][h][sc] = v;
            }
    if ((lane & 3) == 0) {
#pragma unroll
        for (int mf = 0; mf < 2; mf++)
#pragma unroll
            for (int h = 0; h < 2; h++) {
                int r = wm * 32 + mf * 16 + q + h * 8;
                redp[(wn * BM + r) * 2 + 0] = sp[mf][h][0];
                redp[(wn * BM + r) * 2 + 1] = sp[mf][h][1];
            }
    }
    __syncthreads();
    if (tid < BM) {
        int m = m0 + tid;
        if (m < M) {
            Ss[(size_t)m * sstride + bidy] = redp[tid * 2] + redp[(BM + tid) * 2];
            Sd[(size_t)m * sstride + bidy] = redp[tid * 2 + 1] + redp[(BM + tid) * 2 + 1];
        }
    }
}

// ---------------- layer-1 aggregation (8 heads fused, fp16 gather) ---------
__global__ __launch_bounds__(128) void k_agg1(int n_off) {
    int n = blockIdx.x + n_off, t = threadIdx.x;
    int head = t >> 4;
    float ss = g_S1s[n * NHEADS + head];
    float4 a0 = make_float4(0.f, 0.f, 0.f, 0.f);
    float4 a1 = make_float4(0.f, 0.f, 0.f, 0.f);
    float4 a2 = make_float4(0.f, 0.f, 0.f, 0.f);
    float4 a3 = make_float4(0.f, 0.f, 0.f, 0.f);
    float r0 = 0.f, r1 = 0.f, r2 = 0.f, r3 = 0.f;
    int beg = g_rowptr[n], end = g_rowptr[n + 1];
    int e = beg;
    for (; e + 3 < end; e += 4) {
        int d0 = g_dsts[e], d1 = g_dsts[e + 1], d2 = g_dsts[e + 2], d3 = g_dsts[e + 3];
        float s0 = g_S1d[d0 * NHEADS + head];
        float s1 = g_S1d[d1 * NHEADS + head];
        float s2 = g_S1d[d2 * NHEADS + head];
        float s3 = g_S1d[d3 * NHEADS + head];
        float4 h0 = ldh4(&g_H1h[(size_t)d0 * D1 + t * 4]);
        float4 h1 = ldh4(&g_H1h[(size_t)d1 * D1 + t * 4]);
        float4 h2 = ldh4(&g_H1h[(size_t)d2 * D1 + t * 4]);
        float4 h3 = ldh4(&g_H1h[(size_t)d3 * D1 + t * 4]);
        float w0 = __expf(-leakyv(ss + s0));
        float w1 = __expf(-leakyv(ss + s1));
        float w2 = __expf(-leakyv(ss + s2));
        float w3 = __expf(-leakyv(ss + s3));
        a0.x = fmaf(w0, h0.x, a0.x); a0.y = fmaf(w0, h0.y, a0.y);
        a0.z = fmaf(w0, h0.z, a0.z); a0.w = fmaf(w0, h0.w, a0.w);
        a1.x = fmaf(w1, h1.x, a1.x); a1.y = fmaf(w1, h1.y, a1.y);
        a1.z = fmaf(w1, h1.z, a1.z); a1.w = fmaf(w1, h1.w, a1.w);
        a2.x = fmaf(w2, h2.x, a2.x); a2.y = fmaf(w2, h2.y, a2.y);
        a2.z = fmaf(w2, h2.z, a2.z); a2.w = fmaf(w2, h2.w, a2.w);
        a3.x = fmaf(w3, h3.x, a3.x); a3.y = fmaf(w3, h3.y, a3.y);
        a3.z = fmaf(w3, h3.z, a3.z); a3.w = fmaf(w3, h3.w, a3.w);
        r0 += w0; r1 += w1; r2 += w2; r3 += w3;
    }
    for (; e < end; e++) {
        int d0 = g_dsts[e];
        float s0 = g_S1d[d0 * NHEADS + head];
        float4 h0 = ldh4(&g_H1h[(size_t)d0 * D1 + t * 4]);
        float w0 = __expf(-leakyv(ss + s0));
        a0.x = fmaf(w0, h0.x, a0.x); a0.y = fmaf(w0, h0.y, a0.y);
        a0.z = fmaf(w0, h0.z, a0.z); a0.w = fmaf(w0, h0.w, a0.w);
        r0 += w0;
    }
    float inv = 1.f / ((r0 + r1) + (r2 + r3));
    float o[4] = { eluv((a0.x + a1.x + a2.x + a3.x) * inv),
                   eluv((a0.y + a1.y + a2.y + a3.y) * inv),
                   eluv((a0.z + a1.z + a2.z + a3.z) * inv),
                   eluv((a0.w + a1.w + a2.w + a3.w) * inv) };
    size_t base = (size_t)n * D1 + t * 4;
    __nv_bfloat16 hh[4], ll[4];
#pragma unroll
    for (int j = 0; j < 4; j++) {
        hh[j] = __float2bfloat16(o[j]);
        ll[j] = __float2bfloat16(o[j] - __bfloat162float(hh[j]));
    }
    __nv_bfloat162* ph = (__nv_bfloat162*)&g_xch[base];
    __nv_bfloat162* pl = (__nv_bfloat162*)&g_xcl[base];
    ph[0] = __halves2bfloat162(hh[0], hh[1]); ph[1] = __halves2bfloat162(hh[2], hh[3]);
    pl[0] = __halves2bfloat162(ll[0], ll[1]); pl[1] = __halves2bfloat162(ll[2], ll[3]);
}

// ---------------- layer-2 aggregation + fused classifier (fp16 gather) -----
__global__ __launch_bounds__(128) void k_agg2f(const float* __restrict__ mw,
                                               const float* __restrict__ mb,
                                               float* __restrict__ out) {
    __shared__ float xos[2][FH];
    int sub = threadIdx.x >> 6, t = threadIdx.x & 63;
    int n = blockIdx.x * 2 + sub;
    float ss = g_S2s[n];
    float acc0 = 0.f, acc1 = 0.f, rs0 = 0.f, rs1 = 0.f;
    int beg = g_rowptr[n], end = g_rowptr[n + 1];
    int e = beg;
    for (; e + 1 < end; e += 2) {
        int d0 = g_dsts[e], d1 = g_dsts[e + 1];
        float sd0 = g_S2d[d0], sd1 = g_S2d[d1];
        float v0 = __half2float(g_H2h[(size_t)d0 * FH + t]);
        float v1 = __half2float(g_H2h[(size_t)d1 * FH + t]);
        float w0 = __expf(-leakyv(ss + sd0));
        float w1 = __expf(-leakyv(ss + sd1));
        acc0 = fmaf(w0, v0, acc0); rs0 += w0;
        acc1 = fmaf(w1, v1, acc1); rs1 += w1;
    }
    if (e < end) {
        int d0 = g_dsts[e];
        float w0 = __expf(-leakyv(ss + g_S2d[d0]));
        acc0 = fmaf(w0, __half2float(g_H2h[(size_t)d0 * FH + t]), acc0); rs0 += w0;
    }
    xos[sub][t] = eluv((acc0 + acc1) / (rs0 + rs1));
    __syncthreads();
    if (threadIdx.x < 2 * NCLASSF) {
        int s2 = threadIdx.x / NCLASSF, c = threadIdx.x % NCLASSF;
        int n2 = blockIdx.x * 2 + s2;
        const float4* wv = (const float4*)&mw[c * FH];
        const float4* xo = (const float4*)xos[s2];
        float s = mb[c];
#pragma unroll
        for (int k = 0; k < FH / 4; k++) {
            float4 a = xo[k], b = wv[k];
            s = fmaf(a.x, b.x, s); s = fmaf(a.y, b.y, s);
            s = fmaf(a.z, b.z, s); s = fmaf(a.w, b.w, s);
        }
        out[(size_t)n2 * NCLASSF + c] = s;
    }
}

// ---------------- launch (pipelined halves, 3-stream fork-join) -------------
extern "C" void kernel_launch(void* const* d_in, const int* in_sizes, int n_in,
                              void* d_out, int out_size) {
    const float* x  = (const float*)d_in[0];
    const int*   ei = (const int*)d_in[1];
    const float* W  = (const float*)d_in[2];
    const float* a  = (const float*)d_in[3];
    const float* Wo = (const float*)d_in[4];
    const float* ao = (const float*)d_in[5];
    const float* mw = (const float*)d_in[6];
    const float* mb = (const float*)d_in[7];
    float* out = (float*)d_out;

    const int* src = ei;
    const int* dst = ei + N_EDGES;

    float *pS1s, *pS1d, *pS2s, *pS2d;
    __half *pH1h, *pH2h;
    __nv_bfloat16 *pxh, *pxl, *pwth, *pwtl, *pwoth, *pwotl, *pxch, *pxcl;
    cudaGetSymbolAddress((void**)&pH1h, g_H1h);
    cudaGetSymbolAddress((void**)&pH2h, g_H2h);
    cudaGetSymbolAddress((void**)&pS1s, g_S1s);
    cudaGetSymbolAddress((void**)&pS1d, g_S1d);
    cudaGetSymbolAddress((void**)&pS2s, g_S2s);
    cudaGetSymbolAddress((void**)&pS2d, g_S2d);
    cudaGetSymbolAddress((void**)&pxh, g_xh);
    cudaGetSymbolAddress((void**)&pxl, g_xl);
    cudaGetSymbolAddress((void**)&pwth, g_wth);
    cudaGetSymbolAddress((void**)&pwtl, g_wtl);
    cudaGetSymbolAddress((void**)&pwoth, g_woth);
    cudaGetSymbolAddress((void**)&pwotl, g_wotl);
    cudaGetSymbolAddress((void**)&pxch, g_xch);
    cudaGetSymbolAddress((void**)&pxcl, g_xcl);

    cudaFuncSetAttribute(k_gemm_mma, cudaFuncAttributeMaxDynamicSharedMemorySize, GSMEM);

    cudaStream_t s2, s3;
    cudaStreamCreate(&s2);
    cudaStreamCreate(&s3);
    cudaEvent_t evF, evJ, eX1, eA0, eA1, eG2;
    cudaEventCreateWithFlags(&evF, cudaEventDisableTiming);
    cudaEventCreateWithFlags(&evJ, cudaEventDisableTiming);
    cudaEventCreateWithFlags(&eX1, cudaEventDisableTiming);
    cudaEventCreateWithFlags(&eA0, cudaEventDisableTiming);
    cudaEventCreateWithFlags(&eA1, cudaEventDisableTiming);
    cudaEventCreateWithFlags(&eG2, cudaEventDisableTiming);

    const int N0 = MSPLIT, N1 = N_NODES - MSPLIT;   // 25088 / 24912
    const int X0 = N0 * (F_INF / 4);                // float4 count half0
    const int X1 = N1 * (F_INF / 4);

    // fork
    cudaEventRecord(evF, 0);
    cudaStreamWaitEvent(s2, evF, 0);
    cudaStreamWaitEvent(s3, evF, 0);

    // s2: CSR chain + Wo split
    k_zero_cnt<<<(N_NODES + 255) / 256, 256, 0, s2>>>();
    k_hist<<<(N_EDGES + 255) / 256, 256, 0, s2>>>(src);
    k_scan<<<1, 1024, 0, s2>>>();
    k_scatter<<<(N_EDGES + 255) / 256, 256, 0, s2>>>(src, dst);
    k_split_wot<<<(D1 * FH + 255) / 256, 256, 0, s2>>>(Wo, pwoth, pwotl);
    cudaEventRecord(evJ, s2);

    // s3: split_x half1 (overlaps split_x h0 + GEMM1 h0 on main)
    k_split_x<<<(X1 + 255) / 256, 256, 0, s3>>>(x + (size_t)N0 * F_INF,
                                                pxh + (size_t)N0 * F_INF,
                                                pxl + (size_t)N0 * F_INF, X1);
    cudaEventRecord(eX1, s3);

    // main: W split, x split h0, GEMM1 h0
    k_split_wt<<<(NHEADS * F_INF * FH + 255) / 256, 256>>>(W, pwth, pwtl);
    k_split_x<<<(X0 + 255) / 256, 256>>>(x, pxh, pxl, X0);
    dim3 g1a(N0 / BM, NHEADS);
    k_gemm_mma<<<g1a, 256, GSMEM>>>(pxh, pxl, pwth, pwtl, N_NODES, F_INF, 0,
                                    pH1h, D1, a, pS1s, pS1d, NHEADS);
    cudaStreamWaitEvent(0, eX1, 0);
    dim3 g1b((N1 + BM - 1) / BM, NHEADS);
    k_gemm_mma<<<g1b, 256, GSMEM>>>(pxh, pxl, pwth, pwtl, N_NODES, F_INF, N0,
                                    pH1h, D1, a, pS1s, pS1d, NHEADS);

    // agg1 halves (need CSR + full H1)
    cudaStreamWaitEvent(0, evJ, 0);
    k_agg1<<<N0, 128>>>(0);
    cudaEventRecord(eA0, 0);
    k_agg1<<<N1, 128>>>(N0);
    cudaEventRecord(eA1, 0);

    // s2: GEMM2 halves overlap agg1 h1
    cudaStreamWaitEvent(s2, eA0, 0);
    dim3 g2a(N0 / BM, 1);
    k_gemm_mma<<<g2a, 256, GSMEM, s2>>>(pxch, pxcl, pwoth, pwotl, N_NODES, D1, 0,
                                        pH2h, FH, ao, pS2s, pS2d, 1);
    cudaStreamWaitEvent(s2, eA1, 0);
    dim3 g2b((N1 + BM - 1) / BM, 1);
    k_gemm_mma<<<g2b, 256, GSMEM, s2>>>(pxch, pxcl, pwoth, pwotl, N_NODES, D1, N0,
                                        pH2h, FH, ao, pS2s, pS2d, 1);
    cudaEventRecord(eG2, s2);

    // main: final aggregation + classifier
    cudaStreamWaitEvent(0, eG2, 0);
    k_agg2f<<<N_NODES / 2, 128>>>(mw, mb, out);

    cudaEventDestroy(evF); cudaEventDestroy(evJ); cudaEventDestroy(eX1);
    cudaEventDestroy(eA0); cudaEventDestroy(eA1); cudaEventDestroy(eG2);
    cudaStreamDestroy(s2); cudaStreamDestroy(s3);
}

// round 11
// speedup vs baseline: 1.0633x; 1.0633x over previous
#include <cuda_runtime.h>
#include <cuda_bf16.h>
#include <cuda_fp16.h>
#include <cstdint>

#define N_NODES 50000
#define N_EDGES 850000
#define F_INF   256
#define FH      64
#define NHEADS  8
#define NCLASSF 40
#define ALPHAF  0.2f
#define D1      (NHEADS * FH)   // 512

// ---------------- device scratch ----------------
__device__ __half g_H1h[(size_t)N_NODES * D1];   // layer-1 features (fp16)
__device__ __half g_H2h[(size_t)N_NODES * FH];   // layer-2 features (fp16)
__device__ float g_S1s[N_NODES * NHEADS];
__device__ float g_S1d[N_NODES * NHEADS];
__device__ float g_S2s[N_NODES];
__device__ float g_S2d[N_NODES];
__device__ int   g_rowptr[N_NODES + 1];
__device__ int   g_cnt[N_NODES];
__device__ int   g_pos[N_NODES];
__device__ int   g_dsts[N_EDGES];
// bf16 split operands
__device__ __nv_bfloat16 g_xh[(size_t)N_NODES * F_INF];
__device__ __nv_bfloat16 g_xl[(size_t)N_NODES * F_INF];
__device__ __nv_bfloat16 g_wth[NHEADS * FH * F_INF];
__device__ __nv_bfloat16 g_wtl[NHEADS * FH * F_INF];
__device__ __nv_bfloat16 g_woth[FH * D1];
__device__ __nv_bfloat16 g_wotl[FH * D1];
__device__ __nv_bfloat16 g_xch[(size_t)N_NODES * D1];
__device__ __nv_bfloat16 g_xcl[(size_t)N_NODES * D1];

__device__ __forceinline__ float leakyv(float v) { return v > 0.f ? v : ALPHAF * v; }
__device__ __forceinline__ float eluv(float v)   { return v > 0.f ? v : expm1f(v); }
__device__ __forceinline__ float4 ldh4(const __half* p) {
    uint2 u = *(const uint2*)p;
    __half2 h0 = *reinterpret_cast<__half2*>(&u.x);
    __half2 h1 = *reinterpret_cast<__half2*>(&u.y);
    float2 f0 = __half22float2(h0), f1 = __half22float2(h1);
    return make_float4(f0.x, f0.y, f1.x, f1.y);
}

// ---------------- CSR build ----------------
__global__ void k_zero_cnt() {
    int i = blockIdx.x * blockDim.x + threadIdx.x;
    if (i < N_NODES) g_cnt[i] = 0;
}
__global__ void k_hist(const int* __restrict__ src) {
    int e = blockIdx.x * blockDim.x + threadIdx.x;
    if (e < N_EDGES) atomicAdd(&g_cnt[src[e]], 1);
}
__global__ __launch_bounds__(1024) void k_scan() {
    __shared__ int s[1024];
    const int CH = 49;
    int t = threadIdx.x;
    int start = t * CH;
    int end = start + CH; if (end > N_NODES) end = N_NODES;
    int sum = 0;
    for (int i = start; i < end; i++) sum += g_cnt[i];
    s[t] = sum;
    __syncthreads();
    for (int off = 1; off < 1024; off <<= 1) {
        int v = (t >= off) ? s[t - off] : 0;
        __syncthreads();
        s[t] += v;
        __syncthreads();
    }
    int run = (t == 0) ? 0 : s[t - 1];
    for (int i = start; i < end; i++) {
        g_rowptr[i] = run;
        g_pos[i] = run;
        run += g_cnt[i];
    }
    if (t == 0) g_rowptr[N_NODES] = s[1023];
}
__global__ void k_scatter(const int* __restrict__ src, const int* __restrict__ dst) {
    int e = blockIdx.x * blockDim.x + threadIdx.x;
    if (e < N_EDGES) {
        int p = atomicAdd(&g_pos[src[e]], 1);
        g_dsts[p] = dst[e];
    }
}

// ---------------- bf16 hi/lo splits ----------------
__global__ void k_split_x(const float* __restrict__ x, __nv_bfloat16* __restrict__ oh,
                          __nv_bfloat16* __restrict__ ol, int n4) {
    int i = blockIdx.x * blockDim.x + threadIdx.x;
    if (i >= n4) return;
    float4 v = ((const float4*)x)[i];
    __nv_bfloat16 h0 = __float2bfloat16(v.x), h1 = __float2bfloat16(v.y);
    __nv_bfloat16 h2 = __float2bfloat16(v.z), h3 = __float2bfloat16(v.w);
    __nv_bfloat16 l0 = __float2bfloat16(v.x - __bfloat162float(h0));
    __nv_bfloat16 l1 = __float2bfloat16(v.y - __bfloat162float(h1));
    __nv_bfloat16 l2 = __float2bfloat16(v.z - __bfloat162float(h2));
    __nv_bfloat16 l3 = __float2bfloat16(v.w - __bfloat162float(h3));
    __nv_bfloat162* ph = (__nv_bfloat162*)(oh) + i * 2;
    __nv_bfloat162* pl = (__nv_bfloat162*)(ol) + i * 2;
    ph[0] = __halves2bfloat162(h0, h1); ph[1] = __halves2bfloat162(h2, h3);
    pl[0] = __halves2bfloat162(l0, l1); pl[1] = __halves2bfloat162(l2, l3);
}
// W[h][k][n] (fp32) -> out[h][n][k] bf16 hi/lo
__global__ void k_split_wt(const float* __restrict__ W, __nv_bfloat16* __restrict__ oh,
                           __nv_bfloat16* __restrict__ ol) {
    int i = blockIdx.x * blockDim.x + threadIdx.x;
    if (i >= NHEADS * F_INF * FH) return;
    int h = i / (F_INF * FH), r = i % (F_INF * FH), k = r / FH, n = r % FH;
    float v = W[i];
    __nv_bfloat16 hh = __float2bfloat16(v);
    __nv_bfloat16 ll = __float2bfloat16(v - __bfloat162float(hh));
    size_t o = (size_t)(h * FH + n) * F_INF + k;
    oh[o] = hh; ol[o] = ll;
}
// Wo[k][n] -> out[n][k]
__global__ void k_split_wot(const float* __restrict__ Wo, __nv_bfloat16* __restrict__ oh,
                            __nv_bfloat16* __restrict__ ol) {
    int i = blockIdx.x * blockDim.x + threadIdx.x;
    if (i >= D1 * FH) return;
    int k = i / FH, n = i % FH;
    float v = Wo[i];
    __nv_bfloat16 hh = __float2bfloat16(v);
    __nv_bfloat16 ll = __float2bfloat16(v - __bfloat162float(hh));
    size_t o = (size_t)n * D1 + k;
    oh[o] = hh; ol[o] = ll;
}

// ---------------- mma.sync bf16x3 GEMM, 3-stage cp.async pipeline ----------
#define BM 128
#define BN 64
#define BK 32
#define AST 40                      // padded row stride in bf16 (80B)
#define STG 30720                   // bytes per pipeline stage
#define NSTAGE 3
#define OFF_AH 0
#define OFF_AL 10240
#define OFF_BH 20480
#define OFF_BL 25600
#define GSMEM  (NSTAGE * STG + 2048)

__device__ __forceinline__ void mma16816(float* d, const uint32_t* a, const uint32_t* b) {
    asm volatile(
        "mma.sync.aligned.m16n8k16.row.col.f32.bf16.bf16.f32 "
        "{%0,%1,%2,%3},{%4,%5,%6,%7},{%8,%9},{%0,%1,%2,%3};"
        : "+f"(d[0]), "+f"(d[1]), "+f"(d[2]), "+f"(d[3])
        : "r"(a[0]), "r"(a[1]), "r"(a[2]), "r"(a[3]), "r"(b[0]), "r"(b[1]));
}
__device__ __forceinline__ void ldsm4(uint32_t* r, const void* p) {
    uint32_t addr = (uint32_t)__cvta_generic_to_shared(p);
    asm volatile("ldmatrix.sync.aligned.m8n8.x4.shared.b16 {%0,%1,%2,%3}, [%4];"
                 : "=r"(r[0]), "=r"(r[1]), "=r"(r[2]), "=r"(r[3]) : "r"(addr));
}
__device__ __forceinline__ void cp_async16(uint32_t saddr, const void* g, int sz) {
    asm volatile("cp.async.cg.shared.global [%0], [%1], 16, %2;"
                 :: "r"(saddr), "l"(g), "r"(sz));
}
#define CP_COMMIT() asm volatile("cp.async.commit_group;")
#define CP_WAIT0()  asm volatile("cp.async.wait_group 0;")
#define CP_WAIT1()  asm volatile("cp.async.wait_group 1;")

// Output packed fp16 (Ch).
__global__ __launch_bounds__(256) void k_gemm_mma(
    const __nv_bfloat16* __restrict__ Ah, const __nv_bfloat16* __restrict__ Al,
    const __nv_bfloat16* __restrict__ Bh, const __nv_bfloat16* __restrict__ Bl,
    int M, int K, __half* __restrict__ Ch, int ldc,
    const float* __restrict__ att, float* __restrict__ Ss, float* __restrict__ Sd,
    int sstride)
{
    extern __shared__ char sm[];
    uint32_t sbase = (uint32_t)__cvta_generic_to_shared(sm);
    float* redp = (float*)(sm + NSTAGE * STG);   // [2][BM][2]

    int tid = threadIdx.x, lane = tid & 31, wid = tid >> 5;
    int wm = wid & 3, wn = wid >> 2;        // warp grid 4(m) x 2(n)
    int m0 = blockIdx.x * BM;
    int bidy = blockIdx.y;
    Bh += (size_t)bidy * FH * K;
    Bl += (size_t)bidy * FH * K;
    att += bidy * 2 * FH;
    int coloff = bidy * FH;

    float acc[2][4][4];
#pragma unroll
    for (int i = 0; i < 2; i++)
#pragma unroll
        for (int j = 0; j < 4; j++)
#pragma unroll
            for (int l = 0; l < 4; l++) acc[i][j][l] = 0.f;

    int q = lane >> 2, cq = (lane & 3) * 2;

    // per-thread staging map: 6 chunks of 16B; sel: 0 Ah,1 Al,2 Bh,3 Bl
    int st_row[6], st_q[6], st_sel[6];
#pragma unroll
    for (int l = 0; l < 6; l++) {
        int it = tid + l * 256;
        if (it < 1024) {
            int p = it >> 9, i = it & 511;
            st_sel[l] = p; st_row[l] = i >> 2; st_q[l] = i & 3;
        } else {
            int j = it - 1024, p = j >> 8, i = j & 255;
            st_sel[l] = 2 + p; st_row[l] = i >> 2; st_q[l] = i & 3;
        }
    }
    const int seloff[4] = {OFF_AH, OFF_AL, OFF_BH, OFF_BL};

    auto issue_tile = [&](int k0, int slot) {
        uint32_t bo = sbase + slot * STG;
#pragma unroll
        for (int l = 0; l < 6; l++) {
            int row = st_row[l], qq = st_q[l], sel = st_sel[l];
            const __nv_bfloat16* g;
            int sz = 16;
            if (sel < 2) {
                int m = m0 + row;
                if (m >= M) { sz = 0; m = 0; }
                g = (sel ? Al : Ah) + (size_t)m * K + k0 + qq * 8;
            } else {
                g = (sel == 2 ? Bh : Bl) + (size_t)row * K + k0 + qq * 8;
            }
            cp_async16(bo + seloff[sel] + row * 80 + qq * 16, g, sz);
        }
    };

    int nk = K / BK;
    issue_tile(0, 0);
    CP_COMMIT();
    if (nk > 1) { issue_tile(BK, 1); CP_COMMIT(); }

    int arow = lane & 15, ak = (lane >> 4) * 8;
    int brow = (lane & 7) + ((lane >> 4) << 3), bk = ((lane >> 3) & 1) * 8;

    for (int i = 0; i < nk; i++) {
        if (i + 2 < nk) CP_WAIT1(); else CP_WAIT0();
        __syncthreads();
        if (i + 2 < nk) {
            issue_tile((i + 2) * BK, (i + 2) % NSTAGE);
            CP_COMMIT();
        }
        const char* sb = sm + (i % NSTAGE) * STG;
        const __nv_bfloat16* sAh = (const __nv_bfloat16*)(sb + OFF_AH);
        const __nv_bfloat16* sAl = (const __nv_bfloat16*)(sb + OFF_AL);
        const __nv_bfloat16* sBh = (const __nv_bfloat16*)(sb + OFF_BH);
        const __nv_bfloat16* sBl = (const __nv_bfloat16*)(sb + OFF_BL);

#pragma unroll
        for (int kf = 0; kf < 2; kf++) {
            int c0 = kf * 16;
            uint32_t ah[2][4], al[2][4], bhf[4][2], blf[4][2];
#pragma unroll
            for (int mf = 0; mf < 2; mf++) {
                int r = (wm * 32 + mf * 16 + arow) * AST + c0 + ak;
                ldsm4(ah[mf], &sAh[r]);
                ldsm4(al[mf], &sAl[r]);
            }
#pragma unroll
            for (int nfp = 0; nfp < 2; nfp++) {
                int r = (wn * 32 + nfp * 16 + brow) * AST + c0 + bk;
                uint32_t tb[4], tl[4];
                ldsm4(tb, &sBh[r]);
                ldsm4(tl, &sBl[r]);
                bhf[2 * nfp][0] = tb[0]; bhf[2 * nfp][1] = tb[1];
                bhf[2 * nfp + 1][0] = tb[2]; bhf[2 * nfp + 1][1] = tb[3];
                blf[2 * nfp][0] = tl[0]; blf[2 * nfp][1] = tl[1];
                blf[2 * nfp + 1][0] = tl[2]; blf[2 * nfp + 1][1] = tl[3];
            }
#pragma unroll
            for (int mf = 0; mf < 2; mf++)
#pragma unroll
                for (int nf = 0; nf < 4; nf++) {
                    mma16816(acc[mf][nf], ah[mf], bhf[nf]);
                    mma16816(acc[mf][nf], ah[mf], blf[nf]);
                    mma16816(acc[mf][nf], al[mf], bhf[nf]);
                }
        }
    }

    // ---- epilogue: store C packed fp16, fused score dot products ----
    float sp[2][2][2];
#pragma unroll
    for (int mf = 0; mf < 2; mf++)
#pragma unroll
        for (int h = 0; h < 2; h++) { sp[mf][h][0] = 0.f; sp[mf][h][1] = 0.f; }

#pragma unroll
    for (int mf = 0; mf < 2; mf++) {
        int r = wm * 32 + mf * 16 + q;
        int mr = m0 + r;
#pragma unroll
        for (int nf = 0; nf < 4; nf++) {
            int c = wn * 32 + nf * 8 + cq;
            float d0 = acc[mf][nf][0], d1 = acc[mf][nf][1];
            float d2 = acc[mf][nf][2], d3 = acc[mf][nf][3];
            if (mr < M)
                *(__half2*)&Ch[(size_t)mr * ldc + coloff + c] = __floats2half2_rn(d0, d1);
            if (mr + 8 < M)
                *(__half2*)&Ch[(size_t)(mr + 8) * ldc + coloff + c] = __floats2half2_rn(d2, d3);
            float a0 = att[c], a1 = att[c + 1], a2 = att[FH + c], a3 = att[FH + c + 1];
            sp[mf][0][0] = fmaf(d0, a0, fmaf(d1, a1, sp[mf][0][0]));
            sp[mf][0][1] = fmaf(d0, a2, fmaf(d1, a3, sp[mf][0][1]));
            sp[mf][1][0] = fmaf(d2, a0, fmaf(d3, a1, sp[mf][1][0]));
            sp[mf][1][1] = fmaf(d2, a2, fmaf(d3, a3, sp[mf][1][1]));
        }
    }
#pragma unroll
    for (int mf = 0; mf < 2; mf++)
#pragma unroll
        for (int h = 0; h < 2; h++)
#pragma unroll
            for (int sc = 0; sc < 2; sc++) {
                float v = sp[mf][h][sc];
                v += __shfl_xor_sync(0xffffffffu, v, 1);
                v += __shfl_xor_sync(0xffffffffu, v, 2);
                sp[mf][h][sc] = v;
            }
    if ((lane & 3) == 0) {
#pragma unroll
        for (int mf = 0; mf < 2; mf++)
#pragma unroll
            for (int h = 0; h < 2; h++) {
                int r = wm * 32 + mf * 16 + q + h * 8;
                redp[(wn * BM + r) * 2 + 0] = sp[mf][h][0];
                redp[(wn * BM + r) * 2 + 1] = sp[mf][h][1];
            }
    }
    __syncthreads();
    if (tid < BM) {
        int m = m0 + tid;
        if (m < M) {
            Ss[(size_t)m * sstride + bidy] = redp[tid * 2] + redp[(BM + tid) * 2];
            Sd[(size_t)m * sstride + bidy] = redp[tid * 2 + 1] + redp[(BM + tid) * 2 + 1];
        }
    }
}

// ---------------- layer-1 aggregation (8 heads fused, fp16 gather) ---------
__global__ __launch_bounds__(128) void k_agg1() {
    int n = blockIdx.x, t = threadIdx.x;
    int head = t >> 4;
    float ss = g_S1s[n * NHEADS + head];
    float4 a0 = make_float4(0.f, 0.f, 0.f, 0.f);
    float4 a1 = make_float4(0.f, 0.f, 0.f, 0.f);
    float4 a2 = make_float4(0.f, 0.f, 0.f, 0.f);
    float4 a3 = make_float4(0.f, 0.f, 0.f, 0.f);
    float r0 = 0.f, r1 = 0.f, r2 = 0.f, r3 = 0.f;
    int beg = g_rowptr[n], end = g_rowptr[n + 1];
    int e = beg;
    for (; e + 3 < end; e += 4) {
        int d0 = g_dsts[e], d1 = g_dsts[e + 1], d2 = g_dsts[e + 2], d3 = g_dsts[e + 3];
        float s0 = g_S1d[d0 * NHEADS + head];
        float s1 = g_S1d[d1 * NHEADS + head];
        float s2 = g_S1d[d2 * NHEADS + head];
        float s3 = g_S1d[d3 * NHEADS + head];
        float4 h0 = ldh4(&g_H1h[(size_t)d0 * D1 + t * 4]);
        float4 h1 = ldh4(&g_H1h[(size_t)d1 * D1 + t * 4]);
        float4 h2 = ldh4(&g_H1h[(size_t)d2 * D1 + t * 4]);
        float4 h3 = ldh4(&g_H1h[(size_t)d3 * D1 + t * 4]);
        float w0 = __expf(-leakyv(ss + s0));
        float w1 = __expf(-leakyv(ss + s1));
        float w2 = __expf(-leakyv(ss + s2));
        float w3 = __expf(-leakyv(ss + s3));
        a0.x = fmaf(w0, h0.x, a0.x); a0.y = fmaf(w0, h0.y, a0.y);
        a0.z = fmaf(w0, h0.z, a0.z); a0.w = fmaf(w0, h0.w, a0.w);
        a1.x = fmaf(w1, h1.x, a1.x); a1.y = fmaf(w1, h1.y, a1.y);
        a1.z = fmaf(w1, h1.z, a1.z); a1.w = fmaf(w1, h1.w, a1.w);
        a2.x = fmaf(w2, h2.x, a2.x); a2.y = fmaf(w2, h2.y, a2.y);
        a2.z = fmaf(w2, h2.z, a2.z); a2.w = fmaf(w2, h2.w, a2.w);
        a3.x = fmaf(w3, h3.x, a3.x); a3.y = fmaf(w3, h3.y, a3.y);
        a3.z = fmaf(w3, h3.z, a3.z); a3.w = fmaf(w3, h3.w, a3.w);
        r0 += w0; r1 += w1; r2 += w2; r3 += w3;
    }
    for (; e < end; e++) {
        int d0 = g_dsts[e];
        float s0 = g_S1d[d0 * NHEADS + head];
        float4 h0 = ldh4(&g_H1h[(size_t)d0 * D1 + t * 4]);
        float w0 = __expf(-leakyv(ss + s0));
        a0.x = fmaf(w0, h0.x, a0.x); a0.y = fmaf(w0, h0.y, a0.y);
        a0.z = fmaf(w0, h0.z, a0.z); a0.w = fmaf(w0, h0.w, a0.w);
        r0 += w0;
    }
    float inv = 1.f / ((r0 + r1) + (r2 + r3));
    float o[4] = { eluv((a0.x + a1.x + a2.x + a3.x) * inv),
                   eluv((a0.y + a1.y + a2.y + a3.y) * inv),
                   eluv((a0.z + a1.z + a2.z + a3.z) * inv),
                   eluv((a0.w + a1.w + a2.w + a3.w) * inv) };
    size_t base = (size_t)n * D1 + t * 4;
    __nv_bfloat16 hh[4], ll[4];
#pragma unroll
    for (int j = 0; j < 4; j++) {
        hh[j] = __float2bfloat16(o[j]);
        ll[j] = __float2bfloat16(o[j] - __bfloat162float(hh[j]));
    }
    __nv_bfloat162* ph = (__nv_bfloat162*)&g_xch[base];
    __nv_bfloat162* pl = (__nv_bfloat162*)&g_xcl[base];
    ph[0] = __halves2bfloat162(hh[0], hh[1]); ph[1] = __halves2bfloat162(hh[2], hh[3]);
    pl[0] = __halves2bfloat162(ll[0], ll[1]); pl[1] = __halves2bfloat162(ll[2], ll[3]);
}

// ---------------- layer-2 aggregation + fused classifier (fp16 gather) -----
__global__ __launch_bounds__(128) void k_agg2f(const float* __restrict__ mw,
                                               const float* __restrict__ mb,
                                               float* __restrict__ out) {
    __shared__ float xos[2][FH];
    int sub = threadIdx.x >> 6, t = threadIdx.x & 63;
    int n = blockIdx.x * 2 + sub;
    float ss = g_S2s[n];
    float acc0 = 0.f, acc1 = 0.f, rs0 = 0.f, rs1 = 0.f;
    int beg = g_rowptr[n], end = g_rowptr[n + 1];
    int e = beg;
    for (; e + 1 < end; e += 2) {
        int d0 = g_dsts[e], d1 = g_dsts[e + 1];
        float sd0 = g_S2d[d0], sd1 = g_S2d[d1];
        float v0 = __half2float(g_H2h[(size_t)d0 * FH + t]);
        float v1 = __half2float(g_H2h[(size_t)d1 * FH + t]);
        float w0 = __expf(-leakyv(ss + sd0));
        float w1 = __expf(-leakyv(ss + sd1));
        acc0 = fmaf(w0, v0, acc0); rs0 += w0;
        acc1 = fmaf(w1, v1, acc1); rs1 += w1;
    }
    if (e < end) {
        int d0 = g_dsts[e];
        float w0 = __expf(-leakyv(ss + g_S2d[d0]));
        acc0 = fmaf(w0, __half2float(g_H2h[(size_t)d0 * FH + t]), acc0); rs0 += w0;
    }
    xos[sub][t] = eluv((acc0 + acc1) / (rs0 + rs1));
    __syncthreads();
    if (threadIdx.x < 2 * NCLASSF) {
        int s2 = threadIdx.x / NCLASSF, c = threadIdx.x % NCLASSF;
        int n2 = blockIdx.x * 2 + s2;
        const float4* wv = (const float4*)&mw[c * FH];
        const float4* xo = (const float4*)xos[s2];
        float s = mb[c];
#pragma unroll
        for (int k = 0; k < FH / 4; k++) {
            float4 a = xo[k], b = wv[k];
            s = fmaf(a.x, b.x, s); s = fmaf(a.y, b.y, s);
            s = fmaf(a.z, b.z, s); s = fmaf(a.w, b.w, s);
        }
        out[(size_t)n2 * NCLASSF + c] = s;
    }
}

// ---------------- launch (fork-join multi-stream capture, R9 schedule) ------
extern "C" void kernel_launch(void* const* d_in, const int* in_sizes, int n_in,
                              void* d_out, int out_size) {
    const float* x  = (const float*)d_in[0];
    const int*   ei = (const int*)d_in[1];
    const float* W  = (const float*)d_in[2];
    const float* a  = (const float*)d_in[3];
    const float* Wo = (const float*)d_in[4];
    const float* ao = (const float*)d_in[5];
    const float* mw = (const float*)d_in[6];
    const float* mb = (const float*)d_in[7];
    float* out = (float*)d_out;

    const int* src = ei;
    const int* dst = ei + N_EDGES;

    float *pS1s, *pS1d, *pS2s, *pS2d;
    __half *pH1h, *pH2h;
    __nv_bfloat16 *pxh, *pxl, *pwth, *pwtl, *pwoth, *pwotl, *pxch, *pxcl;
    cudaGetSymbolAddress((void**)&pH1h, g_H1h);
    cudaGetSymbolAddress((void**)&pH2h, g_H2h);
    cudaGetSymbolAddress((void**)&pS1s, g_S1s);
    cudaGetSymbolAddress((void**)&pS1d, g_S1d);
    cudaGetSymbolAddress((void**)&pS2s, g_S2s);
    cudaGetSymbolAddress((void**)&pS2d, g_S2d);
    cudaGetSymbolAddress((void**)&pxh, g_xh);
    cudaGetSymbolAddress((void**)&pxl, g_xl);
    cudaGetSymbolAddress((void**)&pwth, g_wth);
    cudaGetSymbolAddress((void**)&pwtl, g_wtl);
    cudaGetSymbolAddress((void**)&pwoth, g_woth);
    cudaGetSymbolAddress((void**)&pwotl, g_wotl);
    cudaGetSymbolAddress((void**)&pxch, g_xch);
    cudaGetSymbolAddress((void**)&pxcl, g_xcl);

    cudaFuncSetAttribute(k_gemm_mma, cudaFuncAttributeMaxDynamicSharedMemorySize, GSMEM);

    cudaStream_t s2, s3;
    cudaStreamCreate(&s2);
    cudaStreamCreate(&s3);
    cudaEvent_t evF, evJ, eW;
    cudaEventCreateWithFlags(&evF, cudaEventDisableTiming);
    cudaEventCreateWithFlags(&evJ, cudaEventDisableTiming);
    cudaEventCreateWithFlags(&eW, cudaEventDisableTiming);

    // fork
    cudaEventRecord(evF, 0);
    cudaStreamWaitEvent(s2, evF, 0);
    cudaStreamWaitEvent(s3, evF, 0);

    // s2: CSR chain + Wo split (hidden under GEMM1)
    k_zero_cnt<<<(N_NODES + 255) / 256, 256, 0, s2>>>();
    k_hist<<<(N_EDGES + 255) / 256, 256, 0, s2>>>(src);
    k_scan<<<1, 1024, 0, s2>>>();
    k_scatter<<<(N_EDGES + 255) / 256, 256, 0, s2>>>(src, dst);
    k_split_wot<<<(D1 * FH + 255) / 256, 256, 0, s2>>>(Wo, pwoth, pwotl);
    cudaEventRecord(evJ, s2);

    // s3: W split (overlaps split_x on main)
    k_split_wt<<<(NHEADS * F_INF * FH + 255) / 256, 256, 0, s3>>>(W, pwth, pwtl);
    cudaEventRecord(eW, s3);

    // main: x split + GEMM1
    k_split_x<<<(N_NODES * F_INF / 4 + 255) / 256, 256>>>(x, pxh, pxl, N_NODES * F_INF / 4);
    cudaStreamWaitEvent(0, eW, 0);
    dim3 g1((N_NODES + BM - 1) / BM, NHEADS);
    k_gemm_mma<<<g1, 256, GSMEM>>>(pxh, pxl, pwth, pwtl, N_NODES, F_INF,
                                   pH1h, D1, a, pS1s, pS1d, NHEADS);

    // join: aggregation needs CSR + GEMM1
    cudaStreamWaitEvent(0, evJ, 0);
    k_agg1<<<N_NODES, 128>>>();

    dim3 g2((N_NODES + BM - 1) / BM, 1);
    k_gemm_mma<<<g2, 256, GSMEM>>>(pxch, pxcl, pwoth, pwotl, N_NODES, D1,
                                   pH2h, FH, ao, pS2s, pS2d, 1);
    k_agg2f<<<N_NODES / 2, 128>>>(mw, mb, out);

    cudaEventDestroy(evF); cudaEventDestroy(evJ); cudaEventDestroy(eW);
    cudaStreamDestroy(s2); cudaStreamDestroy(s3);
}

// round 13
// speedup vs baseline: 1.1756x; 1.1057x over previous
#include <cuda_runtime.h>
#include <cuda_bf16.h>
#include <cuda_fp16.h>
#include <cstdint>

#define N_NODES 50000
#define N_EDGES 850000
#define F_INF   256
#define FH      64
#define NHEADS  8
#define NCLASSF 40
#define ALPHAF  0.2f
#define D1      (NHEADS * FH)   // 512

// ---------------- device scratch ----------------
__device__ __half g_H1h[(size_t)N_NODES * D1];   // layer-1 features (fp16)
__device__ __half g_H2h[(size_t)N_NODES * FH];   // layer-2 features (fp16)
__device__ float g_S1s[N_NODES * NHEADS];
__device__ float g_S1d[N_NODES * NHEADS];
__device__ float g_S2s[N_NODES];
__device__ float g_S2d[N_NODES];
__device__ int   g_rowptr[N_NODES + 1];
__device__ int   g_cnt[N_NODES];
__device__ int   g_pos[N_NODES];
__device__ int   g_dsts[N_EDGES];
// bf16 split operands
__device__ __nv_bfloat16 g_xh[(size_t)N_NODES * F_INF];
__device__ __nv_bfloat16 g_xl[(size_t)N_NODES * F_INF];
__device__ __nv_bfloat16 g_wth[NHEADS * FH * F_INF];
__device__ __nv_bfloat16 g_wtl[NHEADS * FH * F_INF];
__device__ __nv_bfloat16 g_woth[FH * D1];
__device__ __nv_bfloat16 g_wotl[FH * D1];
__device__ __nv_bfloat16 g_xch[(size_t)N_NODES * D1];
__device__ __nv_bfloat16 g_xcl[(size_t)N_NODES * D1];

__device__ __forceinline__ float leakyv(float v) { return v > 0.f ? v : ALPHAF * v; }
__device__ __forceinline__ float eluv(float v)   { return v > 0.f ? v : expm1f(v); }

// ---------------- CSR build ----------------
__global__ void k_zero_cnt() {
    int i = blockIdx.x * blockDim.x + threadIdx.x;
    if (i < N_NODES) g_cnt[i] = 0;
}
__global__ void k_hist(const int* __restrict__ src) {
    int e = blockIdx.x * blockDim.x + threadIdx.x;
    if (e < N_EDGES) atomicAdd(&g_cnt[src[e]], 1);
}
__global__ __launch_bounds__(1024) void k_scan() {
    __shared__ int s[1024];
    const int CH = 49;
    int t = threadIdx.x;
    int start = t * CH;
    int end = start + CH; if (end > N_NODES) end = N_NODES;
    int sum = 0;
    for (int i = start; i < end; i++) sum += g_cnt[i];
    s[t] = sum;
    __syncthreads();
    for (int off = 1; off < 1024; off <<= 1) {
        int v = (t >= off) ? s[t - off] : 0;
        __syncthreads();
        s[t] += v;
        __syncthreads();
    }
    int run = (t == 0) ? 0 : s[t - 1];
    for (int i = start; i < end; i++) {
        g_rowptr[i] = run;
        g_pos[i] = run;
        run += g_cnt[i];
    }
    if (t == 0) g_rowptr[N_NODES] = s[1023];
}
__global__ void k_scatter(const int* __restrict__ src, const int* __restrict__ dst) {
    int e = blockIdx.x * blockDim.x + threadIdx.x;
    if (e < N_EDGES) {
        int p = atomicAdd(&g_pos[src[e]], 1);
        g_dsts[p] = dst[e];
    }
}

// ---------------- bf16 hi/lo splits ----------------
__global__ void k_split_x(const float* __restrict__ x, __nv_bfloat16* __restrict__ oh,
                          __nv_bfloat16* __restrict__ ol, int n4) {
    int i = blockIdx.x * blockDim.x + threadIdx.x;
    if (i >= n4) return;
    float4 v = ((const float4*)x)[i];
    __nv_bfloat16 h0 = __float2bfloat16(v.x), h1 = __float2bfloat16(v.y);
    __nv_bfloat16 h2 = __float2bfloat16(v.z), h3 = __float2bfloat16(v.w);
    __nv_bfloat16 l0 = __float2bfloat16(v.x - __bfloat162float(h0));
    __nv_bfloat16 l1 = __float2bfloat16(v.y - __bfloat162float(h1));
    __nv_bfloat16 l2 = __float2bfloat16(v.z - __bfloat162float(h2));
    __nv_bfloat16 l3 = __float2bfloat16(v.w - __bfloat162float(h3));
    __nv_bfloat162* ph = (__nv_bfloat162*)(oh) + i * 2;
    __nv_bfloat162* pl = (__nv_bfloat162*)(ol) + i * 2;
    ph[0] = __halves2bfloat162(h0, h1); ph[1] = __halves2bfloat162(h2, h3);
    pl[0] = __halves2bfloat162(l0, l1); pl[1] = __halves2bfloat162(l2, l3);
}
// W[h][k][n] (fp32) -> out[h][n][k] bf16 hi/lo
__global__ void k_split_wt(const float* __restrict__ W, __nv_bfloat16* __restrict__ oh,
                           __nv_bfloat16* __restrict__ ol) {
    int i = blockIdx.x * blockDim.x + threadIdx.x;
    if (i >= NHEADS * F_INF * FH) return;
    int h = i / (F_INF * FH), r = i % (F_INF * FH), k = r / FH, n = r % FH;
    float v = W[i];
    __nv_bfloat16 hh = __float2bfloat16(v);
    __nv_bfloat16 ll = __float2bfloat16(v - __bfloat162float(hh));
    size_t o = (size_t)(h * FH + n) * F_INF + k;
    oh[o] = hh; ol[o] = ll;
}
// Wo[k][n] -> out[n][k]
__global__ void k_split_wot(const float* __restrict__ Wo, __nv_bfloat16* __restrict__ oh,
                            __nv_bfloat16* __restrict__ ol) {
    int i = blockIdx.x * blockDim.x + threadIdx.x;
    if (i >= D1 * FH) return;
    int k = i / FH, n = i % FH;
    float v = Wo[i];
    __nv_bfloat16 hh = __float2bfloat16(v);
    __nv_bfloat16 ll = __float2bfloat16(v - __bfloat162float(hh));
    size_t o = (size_t)n * D1 + k;
    oh[o] = hh; ol[o] = ll;
}

// ---------------- mma.sync bf16x3 GEMM, 3-stage cp.async pipeline ----------
#define BM 128
#define BN 64
#define BK 32
#define AST 40                      // padded row stride in bf16 (80B)
#define STG 30720                   // bytes per pipeline stage
#define NSTAGE 3
#define OFF_AH 0
#define OFF_AL 10240
#define OFF_BH 20480
#define OFF_BL 25600
#define GSMEM  (NSTAGE * STG + 2048)

__device__ __forceinline__ void mma16816(float* d, const uint32_t* a, const uint32_t* b) {
    asm volatile(
        "mma.sync.aligned.m16n8k16.row.col.f32.bf16.bf16.f32 "
        "{%0,%1,%2,%3},{%4,%5,%6,%7},{%8,%9},{%0,%1,%2,%3};"
        : "+f"(d[0]), "+f"(d[1]), "+f"(d[2]), "+f"(d[3])
        : "r"(a[0]), "r"(a[1]), "r"(a[2]), "r"(a[3]), "r"(b[0]), "r"(b[1]));
}
__device__ __forceinline__ void ldsm4(uint32_t* r, const void* p) {
    uint32_t addr = (uint32_t)__cvta_generic_to_shared(p);
    asm volatile("ldmatrix.sync.aligned.m8n8.x4.shared.b16 {%0,%1,%2,%3}, [%4];"
                 : "=r"(r[0]), "=r"(r[1]), "=r"(r[2]), "=r"(r[3]) : "r"(addr));
}
__device__ __forceinline__ void cp_async16(uint32_t saddr, const void* g, int sz) {
    asm volatile("cp.async.cg.shared.global [%0], [%1], 16, %2;"
                 :: "r"(saddr), "l"(g), "r"(sz));
}
#define CP_COMMIT() asm volatile("cp.async.commit_group;")
#define CP_WAIT0()  asm volatile("cp.async.wait_group 0;")
#define CP_WAIT1()  asm volatile("cp.async.wait_group 1;")

// Output packed fp16 (Ch).
__global__ __launch_bounds__(256) void k_gemm_mma(
    const __nv_bfloat16* __restrict__ Ah, const __nv_bfloat16* __restrict__ Al,
    const __nv_bfloat16* __restrict__ Bh, const __nv_bfloat16* __restrict__ Bl,
    int M, int K, __half* __restrict__ Ch, int ldc,
    const float* __restrict__ att, float* __restrict__ Ss, float* __restrict__ Sd,
    int sstride)
{
    extern __shared__ char sm[];
    uint32_t sbase = (uint32_t)__cvta_generic_to_shared(sm);
    float* redp = (float*)(sm + NSTAGE * STG);   // [2][BM][2]

    int tid = threadIdx.x, lane = tid & 31, wid = tid >> 5;
    int wm = wid & 3, wn = wid >> 2;        // warp grid 4(m) x 2(n)
    int m0 = blockIdx.x * BM;
    int bidy = blockIdx.y;
    Bh += (size_t)bidy * FH * K;
    Bl += (size_t)bidy * FH * K;
    att += bidy * 2 * FH;
    int coloff = bidy * FH;

    float acc[2][4][4];
#pragma unroll
    for (int i = 0; i < 2; i++)
#pragma unroll
        for (int j = 0; j < 4; j++)
#pragma unroll
            for (int l = 0; l < 4; l++) acc[i][j][l] = 0.f;

    int q = lane >> 2, cq = (lane & 3) * 2;

    // per-thread staging map: 6 chunks of 16B; sel: 0 Ah,1 Al,2 Bh,3 Bl
    int st_row[6], st_q[6], st_sel[6];
#pragma unroll
    for (int l = 0; l < 6; l++) {
        int it = tid + l * 256;
        if (it < 1024) {
            int p = it >> 9, i = it & 511;
            st_sel[l] = p; st_row[l] = i >> 2; st_q[l] = i & 3;
        } else {
            int j = it - 1024, p = j >> 8, i = j & 255;
            st_sel[l] = 2 + p; st_row[l] = i >> 2; st_q[l] = i & 3;
        }
    }
    const int seloff[4] = {OFF_AH, OFF_AL, OFF_BH, OFF_BL};

    auto issue_tile = [&](int k0, int slot) {
        uint32_t bo = sbase + slot * STG;
#pragma unroll
        for (int l = 0; l < 6; l++) {
            int row = st_row[l], qq = st_q[l], sel = st_sel[l];
            const __nv_bfloat16* g;
            int sz = 16;
            if (sel < 2) {
                int m = m0 + row;
                if (m >= M) { sz = 0; m = 0; }
                g = (sel ? Al : Ah) + (size_t)m * K + k0 + qq * 8;
            } else {
                g = (sel == 2 ? Bh : Bl) + (size_t)row * K + k0 + qq * 8;
            }
            cp_async16(bo + seloff[sel] + row * 80 + qq * 16, g, sz);
        }
    };

    int nk = K / BK;
    issue_tile(0, 0);
    CP_COMMIT();
    if (nk > 1) { issue_tile(BK, 1); CP_COMMIT(); }

    int arow = lane & 15, ak = (lane >> 4) * 8;
    int brow = (lane & 7) + ((lane >> 4) << 3), bk = ((lane >> 3) & 1) * 8;

    for (int i = 0; i < nk; i++) {
        if (i + 2 < nk) CP_WAIT1(); else CP_WAIT0();
        __syncthreads();
        if (i + 2 < nk) {
            issue_tile((i + 2) * BK, (i + 2) % NSTAGE);
            CP_COMMIT();
        }
        const char* sb = sm + (i % NSTAGE) * STG;
        const __nv_bfloat16* sAh = (const __nv_bfloat16*)(sb + OFF_AH);
        const __nv_bfloat16* sAl = (const __nv_bfloat16*)(sb + OFF_AL);
        const __nv_bfloat16* sBh = (const __nv_bfloat16*)(sb + OFF_BH);
        const __nv_bfloat16* sBl = (const __nv_bfloat16*)(sb + OFF_BL);

#pragma unroll
        for (int kf = 0; kf < 2; kf++) {
            int c0 = kf * 16;
            uint32_t ah[2][4], al[2][4], bhf[4][2], blf[4][2];
#pragma unroll
            for (int mf = 0; mf < 2; mf++) {
                int r = (wm * 32 + mf * 16 + arow) * AST + c0 + ak;
                ldsm4(ah[mf], &sAh[r]);
                ldsm4(al[mf], &sAl[r]);
            }
#pragma unroll
            for (int nfp = 0; nfp < 2; nfp++) {
                int r = (wn * 32 + nfp * 16 + brow) * AST + c0 + bk;
                uint32_t tb[4], tl[4];
                ldsm4(tb, &sBh[r]);
                ldsm4(tl, &sBl[r]);
                bhf[2 * nfp][0] = tb[0]; bhf[2 * nfp][1] = tb[1];
                bhf[2 * nfp + 1][0] = tb[2]; bhf[2 * nfp + 1][1] = tb[3];
                blf[2 * nfp][0] = tl[0]; blf[2 * nfp][1] = tl[1];
                blf[2 * nfp + 1][0] = tl[2]; blf[2 * nfp + 1][1] = tl[3];
            }
#pragma unroll
            for (int mf = 0; mf < 2; mf++)
#pragma unroll
                for (int nf = 0; nf < 4; nf++) {
                    mma16816(acc[mf][nf], ah[mf], bhf[nf]);
                    mma16816(acc[mf][nf], ah[mf], blf[nf]);
                    mma16816(acc[mf][nf], al[mf], bhf[nf]);
                }
        }
    }

    // ---- epilogue: store C packed fp16, fused score dot products ----
    float sp[2][2][2];
#pragma unroll
    for (int mf = 0; mf < 2; mf++)
#pragma unroll
        for (int h = 0; h < 2; h++) { sp[mf][h][0] = 0.f; sp[mf][h][1] = 0.f; }

#pragma unroll
    for (int mf = 0; mf < 2; mf++) {
        int r = wm * 32 + mf * 16 + q;
        int mr = m0 + r;
#pragma unroll
        for (int nf = 0; nf < 4; nf++) {
            int c = wn * 32 + nf * 8 + cq;
            float d0 = acc[mf][nf][0], d1 = acc[mf][nf][1];
            float d2 = acc[mf][nf][2], d3 = acc[mf][nf][3];
            if (mr < M)
                *(__half2*)&Ch[(size_t)mr * ldc + coloff + c] = __floats2half2_rn(d0, d1);
            if (mr + 8 < M)
                *(__half2*)&Ch[(size_t)(mr + 8) * ldc + coloff + c] = __floats2half2_rn(d2, d3);
            float a0 = att[c], a1 = att[c + 1], a2 = att[FH + c], a3 = att[FH + c + 1];
            sp[mf][0][0] = fmaf(d0, a0, fmaf(d1, a1, sp[mf][0][0]));
            sp[mf][0][1] = fmaf(d0, a2, fmaf(d1, a3, sp[mf][0][1]));
            sp[mf][1][0] = fmaf(d2, a0, fmaf(d3, a1, sp[mf][1][0]));
            sp[mf][1][1] = fmaf(d2, a2, fmaf(d3, a3, sp[mf][1][1]));
        }
    }
#pragma unroll
    for (int mf = 0; mf < 2; mf++)
#pragma unroll
        for (int h = 0; h < 2; h++)
#pragma unroll
            for (int sc = 0; sc < 2; sc++) {
                float v = sp[mf][h][sc];
                v += __shfl_xor_sync(0xffffffffu, v, 1);
                v += __shfl_xor_sync(0xffffffffu, v, 2);
                sp[mf][h][sc] = v;
            }
    if ((lane & 3) == 0) {
#pragma unroll
        for (int mf = 0; mf < 2; mf++)
#pragma unroll
            for (int h = 0; h < 2; h++) {
                int r = wm * 32 + mf * 16 + q + h * 8;
                redp[(wn * BM + r) * 2 + 0] = sp[mf][h][0];
                redp[(wn * BM + r) * 2 + 1] = sp[mf][h][1];
            }
    }
    __syncthreads();
    if (tid < BM) {
        int m = m0 + tid;
        if (m < M) {
            Ss[(size_t)m * sstride + bidy] = redp[tid * 2] + redp[(BM + tid) * 2];
            Sd[(size_t)m * sstride + bidy] = redp[tid * 2 + 1] + redp[(BM + tid) * 2 + 1];
        }
    }
}

// ---------------- layer-1 aggregation (4 nodes/block, 64 thr/node, uint4) --
__global__ __launch_bounds__(256) void k_agg1() {
    int sub = threadIdx.x >> 6;            // node within block
    int n = blockIdx.x * 4 + sub;
    int t = threadIdx.x & 63;              // owns cols t*8 .. t*8+7
    int head = t >> 3;
    float ss = g_S1s[n * NHEADS + head];
    float a0[8], a1[8];
#pragma unroll
    for (int j = 0; j < 8; j++) { a0[j] = 0.f; a1[j] = 0.f; }
    float r0 = 0.f, r1 = 0.f;
    int beg = g_rowptr[n], end = g_rowptr[n + 1];
    int e = beg;
    for (; e + 1 < end; e += 2) {
        int d0 = g_dsts[e], d1 = g_dsts[e + 1];
        float s0 = g_S1d[d0 * NHEADS + head];
        float s1 = g_S1d[d1 * NHEADS + head];
        uint4 u0 = *(const uint4*)&g_H1h[(size_t)d0 * D1 + t * 8];
        uint4 u1 = *(const uint4*)&g_H1h[(size_t)d1 * D1 + t * 8];
        float w0 = __expf(-leakyv(ss + s0));
        float w1 = __expf(-leakyv(ss + s1));
        const __half2* p0 = (const __half2*)&u0;
        const __half2* p1 = (const __half2*)&u1;
#pragma unroll
        for (int j = 0; j < 4; j++) {
            float2 f0 = __half22float2(p0[j]);
            float2 f1 = __half22float2(p1[j]);
            a0[j * 2]     = fmaf(w0, f0.x, a0[j * 2]);
            a0[j * 2 + 1] = fmaf(w0, f0.y, a0[j * 2 + 1]);
            a1[j * 2]     = fmaf(w1, f1.x, a1[j * 2]);
            a1[j * 2 + 1] = fmaf(w1, f1.y, a1[j * 2 + 1]);
        }
        r0 += w0; r1 += w1;
    }
    if (e < end) {
        int d0 = g_dsts[e];
        float s0 = g_S1d[d0 * NHEADS + head];
        uint4 u0 = *(const uint4*)&g_H1h[(size_t)d0 * D1 + t * 8];
        float w0 = __expf(-leakyv(ss + s0));
        const __half2* p0 = (const __half2*)&u0;
#pragma unroll
        for (int j = 0; j < 4; j++) {
            float2 f0 = __half22float2(p0[j]);
            a0[j * 2]     = fmaf(w0, f0.x, a0[j * 2]);
            a0[j * 2 + 1] = fmaf(w0, f0.y, a0[j * 2 + 1]);
        }
        r0 += w0;
    }
    float inv = 1.f / (r0 + r1);
    size_t base = (size_t)n * D1 + t * 8;
    uint4 vh, vl;
    __nv_bfloat162* ph = (__nv_bfloat162*)&vh;
    __nv_bfloat162* pl = (__nv_bfloat162*)&vl;
#pragma unroll
    for (int j = 0; j < 4; j++) {
        float o0 = eluv((a0[j * 2] + a1[j * 2]) * inv);
        float o1 = eluv((a0[j * 2 + 1] + a1[j * 2 + 1]) * inv);
        __nv_bfloat16 h0 = __float2bfloat16(o0);
        __nv_bfloat16 h1 = __float2bfloat16(o1);
        __nv_bfloat16 l0 = __float2bfloat16(o0 - __bfloat162float(h0));
        __nv_bfloat16 l1 = __float2bfloat16(o1 - __bfloat162float(h1));
        ph[j] = __halves2bfloat162(h0, h1);
        pl[j] = __halves2bfloat162(l0, l1);
    }
    *(uint4*)&g_xch[base] = vh;
    *(uint4*)&g_xcl[base] = vl;
}

// ---------------- layer-2 aggregation + fused classifier (half2 gather) ----
__global__ __launch_bounds__(128) void k_agg2f(const float* __restrict__ mw,
                                               const float* __restrict__ mb,
                                               float* __restrict__ out) {
    __shared__ float xos[4][FH];
    int sub = threadIdx.x >> 5, lane = threadIdx.x & 31;
    int n = blockIdx.x * 4 + sub;
    float ss = g_S2s[n];
    float2 acc0 = make_float2(0.f, 0.f), acc1 = make_float2(0.f, 0.f);
    float rs0 = 0.f, rs1 = 0.f;
    int beg = g_rowptr[n], end = g_rowptr[n + 1];
    int e = beg;
    for (; e + 1 < end; e += 2) {
        int d0 = g_dsts[e], d1 = g_dsts[e + 1];
        float sd0 = g_S2d[d0], sd1 = g_S2d[d1];
        __half2 v0 = *(const __half2*)&g_H2h[(size_t)d0 * FH + lane * 2];
        __half2 v1 = *(const __half2*)&g_H2h[(size_t)d1 * FH + lane * 2];
        float w0 = __expf(-leakyv(ss + sd0));
        float w1 = __expf(-leakyv(ss + sd1));
        float2 f0 = __half22float2(v0), f1 = __half22float2(v1);
        acc0.x = fmaf(w0, f0.x, acc0.x); acc0.y = fmaf(w0, f0.y, acc0.y); rs0 += w0;
        acc1.x = fmaf(w1, f1.x, acc1.x); acc1.y = fmaf(w1, f1.y, acc1.y); rs1 += w1;
    }
    if (e < end) {
        int d0 = g_dsts[e];
        float w0 = __expf(-leakyv(ss + g_S2d[d0]));
        float2 f0 = __half22float2(*(const __half2*)&g_H2h[(size_t)d0 * FH + lane * 2]);
        acc0.x = fmaf(w0, f0.x, acc0.x); acc0.y = fmaf(w0, f0.y, acc0.y); rs0 += w0;
    }
    float inv = 1.f / (rs0 + rs1);
    xos[sub][lane * 2]     = eluv((acc0.x + acc1.x) * inv);
    xos[sub][lane * 2 + 1] = eluv((acc0.y + acc1.y) * inv);
    __syncthreads();
    for (int idx = threadIdx.x; idx < 4 * NCLASSF; idx += 128) {
        int s2 = idx / NCLASSF, c = idx % NCLASSF;
        int n2 = blockIdx.x * 4 + s2;
        const float4* wv = (const float4*)&mw[c * FH];
        const float4* xo = (const float4*)xos[s2];
        float s = mb[c];
#pragma unroll
        for (int k = 0; k < FH / 4; k++) {
            float4 a = xo[k], b = wv[k];
            s = fmaf(a.x, b.x, s); s = fmaf(a.y, b.y, s);
            s = fmaf(a.z, b.z, s); s = fmaf(a.w, b.w, s);
        }
        out[(size_t)n2 * NCLASSF + c] = s;
    }
}

// ---------------- launch (fork-join multi-stream capture) -------------------
extern "C" void kernel_launch(void* const* d_in, const int* in_sizes, int n_in,
                              void* d_out, int out_size) {
    const float* x  = (const float*)d_in[0];
    const int*   ei = (const int*)d_in[1];
    const float* W  = (const float*)d_in[2];
    const float* a  = (const float*)d_in[3];
    const float* Wo = (const float*)d_in[4];
    const float* ao = (const float*)d_in[5];
    const float* mw = (const float*)d_in[6];
    const float* mb = (const float*)d_in[7];
    float* out = (float*)d_out;

    const int* src = ei;
    const int* dst = ei + N_EDGES;

    float *pS1s, *pS1d, *pS2s, *pS2d;
    __half *pH1h, *pH2h;
    __nv_bfloat16 *pxh, *pxl, *pwth, *pwtl, *pwoth, *pwotl, *pxch, *pxcl;
    cudaGetSymbolAddress((void**)&pH1h, g_H1h);
    cudaGetSymbolAddress((void**)&pH2h, g_H2h);
    cudaGetSymbolAddress((void**)&pS1s, g_S1s);
    cudaGetSymbolAddress((void**)&pS1d, g_S1d);
    cudaGetSymbolAddress((void**)&pS2s, g_S2s);
    cudaGetSymbolAddress((void**)&pS2d, g_S2d);
    cudaGetSymbolAddress((void**)&pxh, g_xh);
    cudaGetSymbolAddress((void**)&pxl, g_xl);
    cudaGetSymbolAddress((void**)&pwth, g_wth);
    cudaGetSymbolAddress((void**)&pwtl, g_wtl);
    cudaGetSymbolAddress((void**)&pwoth, g_woth);
    cudaGetSymbolAddress((void**)&pwotl, g_wotl);
    cudaGetSymbolAddress((void**)&pxch, g_xch);
    cudaGetSymbolAddress((void**)&pxcl, g_xcl);

    cudaFuncSetAttribute(k_gemm_mma, cudaFuncAttributeMaxDynamicSharedMemorySize, GSMEM);

    cudaStream_t s2, s3;
    cudaStreamCreate(&s2);
    cudaStreamCreate(&s3);
    cudaEvent_t evF, evJ, eW;
    cudaEventCreateWithFlags(&evF, cudaEventDisableTiming);
    cudaEventCreateWithFlags(&evJ, cudaEventDisableTiming);
    cudaEventCreateWithFlags(&eW, cudaEventDisableTiming);

    // fork
    cudaEventRecord(evF, 0);
    cudaStreamWaitEvent(s2, evF, 0);
    cudaStreamWaitEvent(s3, evF, 0);

    // s2: CSR chain + Wo split (hidden under GEMM1)
    k_zero_cnt<<<(N_NODES + 255) / 256, 256, 0, s2>>>();
    k_hist<<<(N_EDGES + 255) / 256, 256, 0, s2>>>(src);
    k_scan<<<1, 1024, 0, s2>>>();
    k_scatter<<<(N_EDGES + 255) / 256, 256, 0, s2>>>(src, dst);
    k_split_wot<<<(D1 * FH + 255) / 256, 256, 0, s2>>>(Wo, pwoth, pwotl);
    cudaEventRecord(evJ, s2);

    // s3: W split (overlaps split_x on main)
    k_split_wt<<<(NHEADS * F_INF * FH + 255) / 256, 256, 0, s3>>>(W, pwth, pwtl);
    cudaEventRecord(eW, s3);

    // main: x split + GEMM1
    k_split_x<<<(N_NODES * F_INF / 4 + 255) / 256, 256>>>(x, pxh, pxl, N_NODES * F_INF / 4);
    cudaStreamWaitEvent(0, eW, 0);
    dim3 g1((N_NODES + BM - 1) / BM, NHEADS);
    k_gemm_mma<<<g1, 256, GSMEM>>>(pxh, pxl, pwth, pwtl, N_NODES, F_INF,
                                   pH1h, D1, a, pS1s, pS1d, NHEADS);

    // join: aggregation needs CSR + GEMM1
    cudaStreamWaitEvent(0, evJ, 0);
    k_agg1<<<(N_NODES + 3) / 4, 256>>>();

    dim3 g2((N_NODES + BM - 1) / BM, 1);
    k_gemm_mma<<<g2, 256, GSMEM>>>(pxch, pxcl, pwoth, pwotl, N_NODES, D1,
                                   pH2h, FH, ao, pS2s, pS2d, 1);
    k_agg2f<<<(N_NODES + 3) / 4, 128>>>(mw, mb, out);

    cudaEventDestroy(evF); cudaEventDestroy(evJ); cudaEventDestroy(eW);
    cudaStreamDestroy(s2); cudaStreamDestroy(s3);
}

// round 15
// speedup vs baseline: 1.2352x; 1.0507x over previous
#include <cuda_runtime.h>
#include <cuda_bf16.h>
#include <cuda_fp16.h>
#include <cstdint>

#define N_NODES 50000
#define N_EDGES 850000
#define F_INF   256
#define FH      64
#define NHEADS  8
#define NCLASSF 40
#define ALPHAF  0.2f
#define D1      (NHEADS * FH)   // 512

// ---------------- device scratch ----------------
__device__ __half g_H1h[(size_t)N_NODES * D1];   // layer-1 features (fp16)
__device__ __half g_H2h[(size_t)N_NODES * FH];   // layer-2 features (fp16)
__device__ float g_S1s[N_NODES * NHEADS];
__device__ float g_S1d[N_NODES * NHEADS];
__device__ float g_S2s[N_NODES];
__device__ float g_S2d[N_NODES];
__device__ int   g_rowptr[N_NODES + 1];
__device__ int   g_cnt[N_NODES];
__device__ int   g_pos[N_NODES];
__device__ int   g_dsts[N_EDGES];
// bf16 split operands
__device__ __nv_bfloat16 g_xh[(size_t)N_NODES * F_INF];
__device__ __nv_bfloat16 g_xl[(size_t)N_NODES * F_INF];
__device__ __nv_bfloat16 g_wth[NHEADS * FH * F_INF];
__device__ __nv_bfloat16 g_wtl[NHEADS * FH * F_INF];
__device__ __nv_bfloat16 g_woth[FH * D1];
__device__ __nv_bfloat16 g_wotl[FH * D1];
__device__ __nv_bfloat16 g_xch[(size_t)N_NODES * D1];
__device__ __nv_bfloat16 g_xcl[(size_t)N_NODES * D1];

__device__ __forceinline__ float leakyv(float v) { return v > 0.f ? v : ALPHAF * v; }
__device__ __forceinline__ float eluv(float v)   { return v > 0.f ? v : expm1f(v); }

// ---------------- CSR build ----------------
__global__ void k_zero_cnt() {
    int i = blockIdx.x * blockDim.x + threadIdx.x;
    if (i < N_NODES) g_cnt[i] = 0;
}
__global__ void k_hist(const int* __restrict__ src) {
    int e = blockIdx.x * blockDim.x + threadIdx.x;
    if (e < N_EDGES) atomicAdd(&g_cnt[src[e]], 1);
}
__global__ __launch_bounds__(1024) void k_scan() {
    __shared__ int s[1024];
    const int CH = 49;
    int t = threadIdx.x;
    int start = t * CH;
    int end = start + CH; if (end > N_NODES) end = N_NODES;
    int sum = 0;
    for (int i = start; i < end; i++) sum += g_cnt[i];
    s[t] = sum;
    __syncthreads();
    for (int off = 1; off < 1024; off <<= 1) {
        int v = (t >= off) ? s[t - off] : 0;
        __syncthreads();
        s[t] += v;
        __syncthreads();
    }
    int run = (t == 0) ? 0 : s[t - 1];
    for (int i = start; i < end; i++) {
        g_rowptr[i] = run;
        g_pos[i] = run;
        run += g_cnt[i];
    }
    if (t == 0) g_rowptr[N_NODES] = s[1023];
}
__global__ void k_scatter(const int* __restrict__ src, const int* __restrict__ dst) {
    int e = blockIdx.x * blockDim.x + threadIdx.x;
    if (e < N_EDGES) {
        int p = atomicAdd(&g_pos[src[e]], 1);
        g_dsts[p] = dst[e];
    }
}

// ---------------- bf16 hi/lo splits ----------------
__global__ void k_split_x(const float* __restrict__ x, __nv_bfloat16* __restrict__ oh,
                          __nv_bfloat16* __restrict__ ol, int n4) {
    int i = blockIdx.x * blockDim.x + threadIdx.x;
    if (i >= n4) return;
    float4 v = ((const float4*)x)[i];
    __nv_bfloat16 h0 = __float2bfloat16(v.x), h1 = __float2bfloat16(v.y);
    __nv_bfloat16 h2 = __float2bfloat16(v.z), h3 = __float2bfloat16(v.w);
    __nv_bfloat16 l0 = __float2bfloat16(v.x - __bfloat162float(h0));
    __nv_bfloat16 l1 = __float2bfloat16(v.y - __bfloat162float(h1));
    __nv_bfloat16 l2 = __float2bfloat16(v.z - __bfloat162float(h2));
    __nv_bfloat16 l3 = __float2bfloat16(v.w - __bfloat162float(h3));
    __nv_bfloat162* ph = (__nv_bfloat162*)(oh) + i * 2;
    __nv_bfloat162* pl = (__nv_bfloat162*)(ol) + i * 2;
    ph[0] = __halves2bfloat162(h0, h1); ph[1] = __halves2bfloat162(h2, h3);
    pl[0] = __halves2bfloat162(l0, l1); pl[1] = __halves2bfloat162(l2, l3);
}
// W[h][k][n] (fp32) -> out[h][n][k] bf16 hi/lo
__global__ void k_split_wt(const float* __restrict__ W, __nv_bfloat16* __restrict__ oh,
                           __nv_bfloat16* __restrict__ ol) {
    int i = blockIdx.x * blockDim.x + threadIdx.x;
    if (i >= NHEADS * F_INF * FH) return;
    int h = i / (F_INF * FH), r = i % (F_INF * FH), k = r / FH, n = r % FH;
    float v = W[i];
    __nv_bfloat16 hh = __float2bfloat16(v);
    __nv_bfloat16 ll = __float2bfloat16(v - __bfloat162float(hh));
    size_t o = (size_t)(h * FH + n) * F_INF + k;
    oh[o] = hh; ol[o] = ll;
}
// Wo[k][n] -> out[n][k]
__global__ void k_split_wot(const float* __restrict__ Wo, __nv_bfloat16* __restrict__ oh,
                            __nv_bfloat16* __restrict__ ol) {
    int i = blockIdx.x * blockDim.x + threadIdx.x;
    if (i >= D1 * FH) return;
    int k = i / FH, n = i % FH;
    float v = Wo[i];
    __nv_bfloat16 hh = __float2bfloat16(v);
    __nv_bfloat16 ll = __float2bfloat16(v - __bfloat162float(hh));
    size_t o = (size_t)n * D1 + k;
    oh[o] = hh; ol[o] = ll;
}

// ---------------- mma.sync bf16x3 GEMM, 3-stage cp.async pipeline ----------
// Grid: (NHEADS_or_1, m_tiles) -> blockIdx.x = head (B select), blockIdx.y = m tile.
#define BM 128
#define BN 64
#define BK 32
#define AST 40                      // padded row stride in bf16 (80B)
#define STG 30720                   // bytes per pipeline stage
#define NSTAGE 3
#define OFF_AH 0
#define OFF_AL 10240
#define OFF_BH 20480
#define OFF_BL 25600
#define GSMEM  (NSTAGE * STG + 2048)

__device__ __forceinline__ void mma16816(float* d, const uint32_t* a, const uint32_t* b) {
    asm volatile(
        "mma.sync.aligned.m16n8k16.row.col.f32.bf16.bf16.f32 "
        "{%0,%1,%2,%3},{%4,%5,%6,%7},{%8,%9},{%0,%1,%2,%3};"
        : "+f"(d[0]), "+f"(d[1]), "+f"(d[2]), "+f"(d[3])
        : "r"(a[0]), "r"(a[1]), "r"(a[2]), "r"(a[3]), "r"(b[0]), "r"(b[1]));
}
__device__ __forceinline__ void ldsm4(uint32_t* r, const void* p) {
    uint32_t addr = (uint32_t)__cvta_generic_to_shared(p);
    asm volatile("ldmatrix.sync.aligned.m8n8.x4.shared.b16 {%0,%1,%2,%3}, [%4];"
                 : "=r"(r[0]), "=r"(r[1]), "=r"(r[2]), "=r"(r[3]) : "r"(addr));
}
__device__ __forceinline__ void cp_async16(uint32_t saddr, const void* g, int sz) {
    asm volatile("cp.async.cg.shared.global [%0], [%1], 16, %2;"
                 :: "r"(saddr), "l"(g), "r"(sz));
}
#define CP_COMMIT() asm volatile("cp.async.commit_group;")
#define CP_WAIT0()  asm volatile("cp.async.wait_group 0;")
#define CP_WAIT1()  asm volatile("cp.async.wait_group 1;")

template <int KT>
__global__ __launch_bounds__(256) void k_gemm_mma(
    const __nv_bfloat16* __restrict__ Ah, const __nv_bfloat16* __restrict__ Al,
    const __nv_bfloat16* __restrict__ Bh, const __nv_bfloat16* __restrict__ Bl,
    int M, __half* __restrict__ Ch, int ldc,
    const float* __restrict__ att, float* __restrict__ Ss, float* __restrict__ Sd,
    int sstride)
{
    extern __shared__ char sm[];
    uint32_t sbase = (uint32_t)__cvta_generic_to_shared(sm);
    float* redp = (float*)(sm + NSTAGE * STG);   // [2][BM][2]

    int tid = threadIdx.x, lane = tid & 31, wid = tid >> 5;
    int wm = wid & 3, wn = wid >> 2;        // warp grid 4(m) x 2(n)
    int m0 = blockIdx.y * BM;               // m tile (slow dim)
    int bidy = blockIdx.x;                  // head (fast dim -> A reuse in L2)
    Bh += (size_t)bidy * FH * KT;
    Bl += (size_t)bidy * FH * KT;
    att += bidy * 2 * FH;
    int coloff = bidy * FH;

    float acc[2][4][4];
#pragma unroll
    for (int i = 0; i < 2; i++)
#pragma unroll
        for (int j = 0; j < 4; j++)
#pragma unroll
            for (int l = 0; l < 4; l++) acc[i][j][l] = 0.f;

    int q = lane >> 2, cq = (lane & 3) * 2;

    // per-thread staging map: 6 chunks of 16B; sel: 0 Ah,1 Al,2 Bh,3 Bl
    int st_row[6], st_q[6], st_sel[6];
#pragma unroll
    for (int l = 0; l < 6; l++) {
        int it = tid + l * 256;
        if (it < 1024) {
            int p = it >> 9, i = it & 511;
            st_sel[l] = p; st_row[l] = i >> 2; st_q[l] = i & 3;
        } else {
            int j = it - 1024, p = j >> 8, i = j & 255;
            st_sel[l] = 2 + p; st_row[l] = i >> 2; st_q[l] = i & 3;
        }
    }
    const int seloff[4] = {OFF_AH, OFF_AL, OFF_BH, OFF_BL};

    auto issue_tile = [&](int k0, int slot) {
        uint32_t bo = sbase + slot * STG;
#pragma unroll
        for (int l = 0; l < 6; l++) {
            int row = st_row[l], qq = st_q[l], sel = st_sel[l];
            const __nv_bfloat16* g;
            int sz = 16;
            if (sel < 2) {
                int m = m0 + row;
                if (m >= M) { sz = 0; m = 0; }
                g = (sel ? Al : Ah) + (size_t)m * KT + k0 + qq * 8;
            } else {
                g = (sel == 2 ? Bh : Bl) + (size_t)row * KT + k0 + qq * 8;
            }
            cp_async16(bo + seloff[sel] + row * 80 + qq * 16, g, sz);
        }
    };

    constexpr int nk = KT / BK;
    issue_tile(0, 0);
    CP_COMMIT();
    issue_tile(BK, 1);
    CP_COMMIT();

    int arow = lane & 15, ak = (lane >> 4) * 8;
    int brow = (lane & 7) + ((lane >> 4) << 3), bk = ((lane >> 3) & 1) * 8;

#pragma unroll
    for (int i = 0; i < nk; i++) {
        if (i + 2 < nk) CP_WAIT1(); else CP_WAIT0();
        __syncthreads();
        if (i + 2 < nk) {
            issue_tile((i + 2) * BK, (i + 2) % NSTAGE);
            CP_COMMIT();
        }
        const char* sb = sm + (i % NSTAGE) * STG;
        const __nv_bfloat16* sAh = (const __nv_bfloat16*)(sb + OFF_AH);
        const __nv_bfloat16* sAl = (const __nv_bfloat16*)(sb + OFF_AL);
        const __nv_bfloat16* sBh = (const __nv_bfloat16*)(sb + OFF_BH);
        const __nv_bfloat16* sBl = (const __nv_bfloat16*)(sb + OFF_BL);

#pragma unroll
        for (int kf = 0; kf < 2; kf++) {
            int c0 = kf * 16;
            uint32_t ah[2][4], al[2][4], bhf[4][2], blf[4][2];
#pragma unroll
            for (int mf = 0; mf < 2; mf++) {
                int r = (wm * 32 + mf * 16 + arow) * AST + c0 + ak;
                ldsm4(ah[mf], &sAh[r]);
                ldsm4(al[mf], &sAl[r]);
            }
#pragma unroll
            for (int nfp = 0; nfp < 2; nfp++) {
                int r = (wn * 32 + nfp * 16 + brow) * AST + c0 + bk;
                uint32_t tb[4], tl[4];
                ldsm4(tb, &sBh[r]);
                ldsm4(tl, &sBl[r]);
                bhf[2 * nfp][0] = tb[0]; bhf[2 * nfp][1] = tb[1];
                bhf[2 * nfp + 1][0] = tb[2]; bhf[2 * nfp + 1][1] = tb[3];
                blf[2 * nfp][0] = tl[0]; blf[2 * nfp][1] = tl[1];
                blf[2 * nfp + 1][0] = tl[2]; blf[2 * nfp + 1][1] = tl[3];
            }
#pragma unroll
            for (int mf = 0; mf < 2; mf++)
#pragma unroll
                for (int nf = 0; nf < 4; nf++) {
                    mma16816(acc[mf][nf], ah[mf], bhf[nf]);
                    mma16816(acc[mf][nf], ah[mf], blf[nf]);
                    mma16816(acc[mf][nf], al[mf], bhf[nf]);
                }
        }
    }

    // ---- epilogue: store C packed fp16, fused score dot products ----
    float sp[2][2][2];
#pragma unroll
    for (int mf = 0; mf < 2; mf++)
#pragma unroll
        for (int h = 0; h < 2; h++) { sp[mf][h][0] = 0.f; sp[mf][h][1] = 0.f; }

#pragma unroll
    for (int mf = 0; mf < 2; mf++) {
        int r = wm * 32 + mf * 16 + q;
        int mr = m0 + r;
#pragma unroll
        for (int nf = 0; nf < 4; nf++) {
            int c = wn * 32 + nf * 8 + cq;
            float d0 = acc[mf][nf][0], d1 = acc[mf][nf][1];
            float d2 = acc[mf][nf][2], d3 = acc[mf][nf][3];
            if (mr < M)
                *(__half2*)&Ch[(size_t)mr * ldc + coloff + c] = __floats2half2_rn(d0, d1);
            if (mr + 8 < M)
                *(__half2*)&Ch[(size_t)(mr + 8) * ldc + coloff + c] = __floats2half2_rn(d2, d3);
            float a0 = att[c], a1 = att[c + 1], a2 = att[FH + c], a3 = att[FH + c + 1];
            sp[mf][0][0] = fmaf(d0, a0, fmaf(d1, a1, sp[mf][0][0]));
            sp[mf][0][1] = fmaf(d0, a2, fmaf(d1, a3, sp[mf][0][1]));
            sp[mf][1][0] = fmaf(d2, a0, fmaf(d3, a1, sp[mf][1][0]));
            sp[mf][1][1] = fmaf(d2, a2, fmaf(d3, a3, sp[mf][1][1]));
        }
    }
#pragma unroll
    for (int mf = 0; mf < 2; mf++)
#pragma unroll
        for (int h = 0; h < 2; h++)
#pragma unroll
            for (int sc = 0; sc < 2; sc++) {
                float v = sp[mf][h][sc];
                v += __shfl_xor_sync(0xffffffffu, v, 1);
                v += __shfl_xor_sync(0xffffffffu, v, 2);
                sp[mf][h][sc] = v;
            }
    if ((lane & 3) == 0) {
#pragma unroll
        for (int mf = 0; mf < 2; mf++)
#pragma unroll
            for (int h = 0; h < 2; h++) {
                int r = wm * 32 + mf * 16 + q + h * 8;
                redp[(wn * BM + r) * 2 + 0] = sp[mf][h][0];
                redp[(wn * BM + r) * 2 + 1] = sp[mf][h][1];
            }
    }
    __syncthreads();
    if (tid < BM) {
        int m = m0 + tid;
        if (m < M) {
            Ss[(size_t)m * sstride + bidy] = redp[tid * 2] + redp[(BM + tid) * 2];
            Sd[(size_t)m * sstride + bidy] = redp[tid * 2 + 1] + redp[(BM + tid) * 2 + 1];
        }
    }
}

// ---------------- layer-1 aggregation (4 nodes/block, 64 thr/node, uint4) --
__global__ __launch_bounds__(256) void k_agg1() {
    int sub = threadIdx.x >> 6;            // node within block
    int n = blockIdx.x * 4 + sub;
    int t = threadIdx.x & 63;              // owns cols t*8 .. t*8+7
    int head = t >> 3;
    float ss = g_S1s[n * NHEADS + head];
    float a0[8], a1[8];
#pragma unroll
    for (int j = 0; j < 8; j++) { a0[j] = 0.f; a1[j] = 0.f; }
    float r0 = 0.f, r1 = 0.f;
    int beg = g_rowptr[n], end = g_rowptr[n + 1];
    int e = beg;
    for (; e + 1 < end; e += 2) {
        int d0 = g_dsts[e], d1 = g_dsts[e + 1];
        float s0 = g_S1d[d0 * NHEADS + head];
        float s1 = g_S1d[d1 * NHEADS + head];
        uint4 u0 = *(const uint4*)&g_H1h[(size_t)d0 * D1 + t * 8];
        uint4 u1 = *(const uint4*)&g_H1h[(size_t)d1 * D1 + t * 8];
        float w0 = __expf(-leakyv(ss + s0));
        float w1 = __expf(-leakyv(ss + s1));
        const __half2* p0 = (const __half2*)&u0;
        const __half2* p1 = (const __half2*)&u1;
#pragma unroll
        for (int j = 0; j < 4; j++) {
            float2 f0 = __half22float2(p0[j]);
            float2 f1 = __half22float2(p1[j]);
            a0[j * 2]     = fmaf(w0, f0.x, a0[j * 2]);
            a0[j * 2 + 1] = fmaf(w0, f0.y, a0[j * 2 + 1]);
            a1[j * 2]     = fmaf(w1, f1.x, a1[j * 2]);
            a1[j * 2 + 1] = fmaf(w1, f1.y, a1[j * 2 + 1]);
        }
        r0 += w0; r1 += w1;
    }
    if (e < end) {
        int d0 = g_dsts[e];
        float s0 = g_S1d[d0 * NHEADS + head];
        uint4 u0 = *(const uint4*)&g_H1h[(size_t)d0 * D1 + t * 8];
        float w0 = __expf(-leakyv(ss + s0));
        const __half2* p0 = (const __half2*)&u0;
#pragma unroll
        for (int j = 0; j < 4; j++) {
            float2 f0 = __half22float2(p0[j]);
            a0[j * 2]     = fmaf(w0, f0.x, a0[j * 2]);
            a0[j * 2 + 1] = fmaf(w0, f0.y, a0[j * 2 + 1]);
        }
        r0 += w0;
    }
    float inv = 1.f / (r0 + r1);
    size_t base = (size_t)n * D1 + t * 8;
    uint4 vh, vl;
    __nv_bfloat162* ph = (__nv_bfloat162*)&vh;
    __nv_bfloat162* pl = (__nv_bfloat162*)&vl;
#pragma unroll
    for (int j = 0; j < 4; j++) {
        float o0 = eluv((a0[j * 2] + a1[j * 2]) * inv);
        float o1 = eluv((a0[j * 2 + 1] + a1[j * 2 + 1]) * inv);
        __nv_bfloat16 h0 = __float2bfloat16(o0);
        __nv_bfloat16 h1 = __float2bfloat16(o1);
        __nv_bfloat16 l0 = __float2bfloat16(o0 - __bfloat162float(h0));
        __nv_bfloat16 l1 = __float2bfloat16(o1 - __bfloat162float(h1));
        ph[j] = __halves2bfloat162(h0, h1);
        pl[j] = __halves2bfloat162(l0, l1);
    }
    *(uint4*)&g_xch[base] = vh;
    *(uint4*)&g_xcl[base] = vl;
}

// ---------------- layer-2 aggregation + fused classifier (half2 gather) ----
__global__ __launch_bounds__(128) void k_agg2f(const float* __restrict__ mw,
                                               const float* __restrict__ mb,
                                               float* __restrict__ out) {
    __shared__ float xos[4][FH];
    int sub = threadIdx.x >> 5, lane = threadIdx.x & 31;
    int n = blockIdx.x * 4 + sub;
    float ss = g_S2s[n];
    float2 acc0 = make_float2(0.f, 0.f), acc1 = make_float2(0.f, 0.f);
    float rs0 = 0.f, rs1 = 0.f;
    int beg = g_rowptr[n], end = g_rowptr[n + 1];
    int e = beg;
    for (; e + 1 < end; e += 2) {
        int d0 = g_dsts[e], d1 = g_dsts[e + 1];
        float sd0 = g_S2d[d0], sd1 = g_S2d[d1];
        __half2 v0 = *(const __half2*)&g_H2h[(size_t)d0 * FH + lane * 2];
        __half2 v1 = *(const __half2*)&g_H2h[(size_t)d1 * FH + lane * 2];
        float w0 = __expf(-leakyv(ss + sd0));
        float w1 = __expf(-leakyv(ss + sd1));
        float2 f0 = __half22float2(v0), f1 = __half22float2(v1);
        acc0.x = fmaf(w0, f0.x, acc0.x); acc0.y = fmaf(w0, f0.y, acc0.y); rs0 += w0;
        acc1.x = fmaf(w1, f1.x, acc1.x); acc1.y = fmaf(w1, f1.y, acc1.y); rs1 += w1;
    }
    if (e < end) {
        int d0 = g_dsts[e];
        float w0 = __expf(-leakyv(ss + g_S2d[d0]));
        float2 f0 = __half22float2(*(const __half2*)&g_H2h[(size_t)d0 * FH + lane * 2]);
        acc0.x = fmaf(w0, f0.x, acc0.x); acc0.y = fmaf(w0, f0.y, acc0.y); rs0 += w0;
    }
    float inv = 1.f / (rs0 + rs1);
    xos[sub][lane * 2]     = eluv((acc0.x + acc1.x) * inv);
    xos[sub][lane * 2 + 1] = eluv((acc0.y + acc1.y) * inv);
    __syncthreads();
    for (int idx = threadIdx.x; idx < 4 * NCLASSF; idx += 128) {
        int s2 = idx / NCLASSF, c = idx % NCLASSF;
        int n2 = blockIdx.x * 4 + s2;
        const float4* wv = (const float4*)&mw[c * FH];
        const float4* xo = (const float4*)xos[s2];
        float s = mb[c];
#pragma unroll
        for (int k = 0; k < FH / 4; k++) {
            float4 a = xo[k], b = wv[k];
            s = fmaf(a.x, b.x, s); s = fmaf(a.y, b.y, s);
            s = fmaf(a.z, b.z, s); s = fmaf(a.w, b.w, s);
        }
        out[(size_t)n2 * NCLASSF + c] = s;
    }
}

// ---------------- launch (fork-join multi-stream capture) -------------------
extern "C" void kernel_launch(void* const* d_in, const int* in_sizes, int n_in,
                              void* d_out, int out_size) {
    const float* x  = (const float*)d_in[0];
    const int*   ei = (const int*)d_in[1];
    const float* W  = (const float*)d_in[2];
    const float* a  = (const float*)d_in[3];
    const float* Wo = (const float*)d_in[4];
    const float* ao = (const float*)d_in[5];
    const float* mw = (const float*)d_in[6];
    const float* mb = (const float*)d_in[7];
    float* out = (float*)d_out;

    const int* src = ei;
    const int* dst = ei + N_EDGES;

    float *pS1s, *pS1d, *pS2s, *pS2d;
    __half *pH1h, *pH2h;
    __nv_bfloat16 *pxh, *pxl, *pwth, *pwtl, *pwoth, *pwotl, *pxch, *pxcl;
    cudaGetSymbolAddress((void**)&pH1h, g_H1h);
    cudaGetSymbolAddress((void**)&pH2h, g_H2h);
    cudaGetSymbolAddress((void**)&pS1s, g_S1s);
    cudaGetSymbolAddress((void**)&pS1d, g_S1d);
    cudaGetSymbolAddress((void**)&pS2s, g_S2s);
    cudaGetSymbolAddress((void**)&pS2d, g_S2d);
    cudaGetSymbolAddress((void**)&pxh, g_xh);
    cudaGetSymbolAddress((void**)&pxl, g_xl);
    cudaGetSymbolAddress((void**)&pwth, g_wth);
    cudaGetSymbolAddress((void**)&pwtl, g_wtl);
    cudaGetSymbolAddress((void**)&pwoth, g_woth);
    cudaGetSymbolAddress((void**)&pwotl, g_wotl);
    cudaGetSymbolAddress((void**)&pxch, g_xch);
    cudaGetSymbolAddress((void**)&pxcl, g_xcl);

    cudaFuncSetAttribute(k_gemm_mma<256>, cudaFuncAttributeMaxDynamicSharedMemorySize, GSMEM);
    cudaFuncSetAttribute(k_gemm_mma<512>, cudaFuncAttributeMaxDynamicSharedMemorySize, GSMEM);

    cudaStream_t s2, s3;
    cudaStreamCreate(&s2);
    cudaStreamCreate(&s3);
    cudaEvent_t evF, evJ, eW;
    cudaEventCreateWithFlags(&evF, cudaEventDisableTiming);
    cudaEventCreateWithFlags(&evJ, cudaEventDisableTiming);
    cudaEventCreateWithFlags(&eW, cudaEventDisableTiming);

    // fork
    cudaEventRecord(evF, 0);
    cudaStreamWaitEvent(s2, evF, 0);
    cudaStreamWaitEvent(s3, evF, 0);

    // s2: CSR chain + Wo split (hidden under GEMM1)
    k_zero_cnt<<<(N_NODES + 255) / 256, 256, 0, s2>>>();
    k_hist<<<(N_EDGES + 255) / 256, 256, 0, s2>>>(src);
    k_scan<<<1, 1024, 0, s2>>>();
    k_scatter<<<(N_EDGES + 255) / 256, 256, 0, s2>>>(src, dst);
    k_split_wot<<<(D1 * FH + 255) / 256, 256, 0, s2>>>(Wo, pwoth, pwotl);
    cudaEventRecord(evJ, s2);

    // s3: W split (overlaps split_x on main)
    k_split_wt<<<(NHEADS * F_INF * FH + 255) / 256, 256, 0, s3>>>(W, pwth, pwtl);
    cudaEventRecord(eW, s3);

    // main: x split + GEMM1 (head-fast grid for A reuse in L2)
    k_split_x<<<(N_NODES * F_INF / 4 + 255) / 256, 256>>>(x, pxh, pxl, N_NODES * F_INF / 4);
    cudaStreamWaitEvent(0, eW, 0);
    dim3 g1(NHEADS, (N_NODES + BM - 1) / BM);
    k_gemm_mma<256><<<g1, 256, GSMEM>>>(pxh, pxl, pwth, pwtl, N_NODES,
                                        pH1h, D1, a, pS1s, pS1d, NHEADS);

    // join: aggregation needs CSR + GEMM1
    cudaStreamWaitEvent(0, evJ, 0);
    k_agg1<<<(N_NODES + 3) / 4, 256>>>();

    dim3 g2(1, (N_NODES + BM - 1) / BM);
    k_gemm_mma<512><<<g2, 256, GSMEM>>>(pxch, pxcl, pwoth, pwotl, N_NODES,
                                        pH2h, FH, ao, pS2s, pS2d, 1);
    k_agg2f<<<(N_NODES + 3) / 4, 128>>>(mw, mb, out);

    cudaEventDestroy(evF); cudaEventDestroy(evJ); cudaEventDestroy(eW);
    cudaStreamDestroy(s2); cudaStreamDestroy(s3);
}